// round 9
// baseline (speedup 1.0000x reference)
#include <cuda_runtime.h>
#include <cuda_bf16.h>
#include <math.h>

// Problem constants
#define BB 2
#define EE 1024
#define SS 2048
#define HH 16
#define DD 64
#define BES (BB*EE*SS)          // 4,194,304 elements

// ---------------------------------------------------------------------------
// Scratch (device globals; no runtime allocation allowed)
// ---------------------------------------------------------------------------
__device__ float g_ql[BES], g_kl[BES], g_vl[BES];
__device__ float g_qr[BES], g_kr[BES], g_vr[BES];
__device__ float g_al[BES], g_ar[BES];
__device__ float g_h1[2 * BES];
__device__ float g_wf[2 * EE * EE];
__device__ float g_lam;

// Packed bf16-pair planes: one u32 word = (bf16 of elem 2i, bf16 of elem 2i+1)
__device__ unsigned g_lh[BES/2],  g_ll[BES/2];     // left  (B-pack over [B*E,S])
__device__ unsigned g_rh[BES/2],  g_rl[BES/2];     // right
__device__ unsigned g_wh[6*EE*EE/2], g_wl[6*EE*EE/2];  // 6 QKV weights (A-pack)
__device__ unsigned g_w1h[EE*EE], g_w1l[EE*EE];    // W1 [2E,E] A-pack -> 1M words
__device__ unsigned g_w2h[EE*EE], g_w2l[EE*EE];    // W2 [E,2E] A-pack
__device__ unsigned g_woh[EE*EE/2], g_wol[EE*EE/2];// Wo [E,E] B-pack
__device__ unsigned g_wfh[EE*EE], g_wfl[EE*EE];    // wf [2E,E] A-pack
__device__ unsigned g_lnh[BES/2], g_lnl[BES/2];    // LN out (B-pack)
__device__ unsigned g_h1h[BES],   g_h1l[BES];      // h1 [B*2E,S] B-pack

// ---------------------------------------------------------------------------
// bf16 split helpers
// ---------------------------------------------------------------------------
__device__ __forceinline__ unsigned bf2pack(float x, float y) {
    __nv_bfloat162 h = __floats2bfloat162_rn(x, y);
    return *reinterpret_cast<unsigned*>(&h);
}
__device__ __forceinline__ float bfhi(float x) {
    return __bfloat162float(__float2bfloat16(x));
}
__device__ __forceinline__ void mma_bf16(
    float& c0, float& c1, float& c2, float& c3,
    unsigned a0, unsigned a1, unsigned a2, unsigned a3,
    unsigned b0, unsigned b1)
{
    asm("mma.sync.aligned.m16n8k16.row.col.f32.bf16.bf16.f32 "
        "{%0,%1,%2,%3}, {%4,%5,%6,%7}, {%8,%9}, {%0,%1,%2,%3};"
        : "+f"(c0), "+f"(c1), "+f"(c2), "+f"(c3)
        : "r"(a0), "r"(a1), "r"(a2), "r"(a3), "r"(b0), "r"(b1));
}

// exp2 via FMA-pipe polynomial (degree-5, rel ~2e-6) — dodges MUFU ceiling.
__device__ __forceinline__ float exp2p(float z) {
    z = fmaxf(z, -100.f);
    float n = rintf(z);
    float f = z - n;
    float p = 0.00133335581f;
    p = fmaf(p, f, 0.00961812911f);
    p = fmaf(p, f, 0.05550410866f);
    p = fmaf(p, f, 0.24022650696f);
    p = fmaf(p, f, 0.69314718056f);
    p = fmaf(p, f, 1.0f);
    float sc = __int_as_float(((int)n + 127) << 23);
    return p * sc;
}

// ---------------------------------------------------------------------------
// Pack kernels: fp32 -> (hi, lo) bf16-pair planes.
// pack_a: pair along the CONTIGUOUS axis (weights [M,K], k contiguous).
//   word i <=> float2 at src[2i].
// pack_b: pair along the STRIDED axis (activations [K,N], n contiguous).
//   word(k2*N + n) = (src[2k2][n], src[2k2+1][n]).
// ---------------------------------------------------------------------------
__global__ void pack_a(const float* __restrict__ src, unsigned* __restrict__ h,
                       unsigned* __restrict__ l, int n2)
{
    int i = blockIdx.x * 256 + threadIdx.x;
    if (i >= n2) return;
    float2 v = ((const float2*)src)[i];
    h[i] = bf2pack(v.x, v.y);
    l[i] = bf2pack(v.x - bfhi(v.x), v.y - bfhi(v.y));
}

__global__ void pack_b(const float* __restrict__ src, unsigned* __restrict__ h,
                       unsigned* __restrict__ l, int N)
{
    int n = blockIdx.x * 256 + threadIdx.x;   // grid.x = N/256
    int k2 = blockIdx.y;                      // grid.y = K/2
    size_t w = (size_t)k2 * N + n;
    float a = src[(size_t)(2 * k2) * N + n];
    float b = src[(size_t)(2 * k2 + 1) * N + n];
    h[w] = bf2pack(a, b);
    l[w] = bf2pack(a - bfhi(a), b - bfhi(b));
}

// ---------------------------------------------------------------------------
// Tensor-core GEMM body (3-product split-bf16 m16n8k16), double-buffered.
// All operands PRE-SPLIT packed planes -> loader is pure word moves; the
// compute/SMEM layout is identical to the verified round-8 kernel.
// A planes: word(m*(K/2) + k2). B planes: word(k2*N + n).
// Per-buffer word layout: Ah[0..1023] Al[1024..2047] Bh[2048..3071] Bl[3072..4095]
// ---------------------------------------------------------------------------
#define GEMM_SMEM (2 * 4096 * 4)

__device__ __forceinline__ void gemm_body(
    const unsigned* __restrict__ Ahg, const unsigned* __restrict__ Alg,
    const unsigned* __restrict__ Bhg, const unsigned* __restrict__ Blg,
    float* __restrict__ Cb, int M, int K, int N,
    const float* __restrict__ bias, float alpha, int relu,
    unsigned* smp)
{
    const int t = threadIdx.x;
    const int lane = t & 31, wid = t >> 5;
    const int warpM = wid >> 2, warpN = wid & 3;
    const int bm = blockIdx.y << 7, bn = blockIdx.x << 7;
    const int K2 = K >> 1;

    float acc[4][4][4];
#pragma unroll
    for (int a = 0; a < 4; ++a)
#pragma unroll
        for (int b = 0; b < 4; ++b)
#pragma unroll
            for (int c = 0; c < 4; ++c) acc[a][b][c] = 0.f;

    const int amt = t >> 5, als = t & 31;
    const int amo = (amt << 4) + (als >> 2);
    const int ako = (als & 3) << 1;
    int bno[2], bko[2];
#pragma unroll
    for (int i = 0; i < 2; ++i) {
        int s = t + (i << 8), nt = s >> 5, ls = s & 31;
        bno[i] = (nt << 3) + (ls >> 2);
        bko[i] = (ls & 3) << 1;
    }

    unsigned pah[4], pal[4], pbh[2][2], pbl[2][2];

    auto loadG = [&](int k0) {
        size_t ab = (size_t)(bm + amo) * K2 + ((k0 + ako) >> 1);
        const unsigned* ah = Ahg + ab;
        const unsigned* al = Alg + ab;
        pah[0] = ah[0]; pah[1] = ah[(size_t)8 * K2];
        pah[2] = ah[4]; pah[3] = ah[(size_t)8 * K2 + 4];
        pal[0] = al[0]; pal[1] = al[(size_t)8 * K2];
        pal[2] = al[4]; pal[3] = al[(size_t)8 * K2 + 4];
#pragma unroll
        for (int i = 0; i < 2; ++i) {
            size_t bb = (size_t)((k0 + bko[i]) >> 1) * N + bn + bno[i];
            pbh[i][0] = Bhg[bb]; pbh[i][1] = Bhg[bb + (size_t)4 * N];
            pbl[i][0] = Blg[bb]; pbl[i][1] = Blg[bb + (size_t)4 * N];
        }
    };

    auto storeS = [&](int buf) {
        unsigned* Ah = smp + buf * 4096;
        unsigned* Al = smp + buf * 4096 + 1024;
        unsigned* Bh = smp + buf * 4096 + 2048;
        unsigned* Bl = smp + buf * 4096 + 3072;
        *(uint4*)&Ah[t * 4] = make_uint4(pah[0], pah[1], pah[2], pah[3]);
        *(uint4*)&Al[t * 4] = make_uint4(pal[0], pal[1], pal[2], pal[3]);
#pragma unroll
        for (int i = 0; i < 2; ++i) {
            int s = t + (i << 8);
            *(uint2*)&Bh[s * 2] = make_uint2(pbh[i][0], pbh[i][1]);
            *(uint2*)&Bl[s * 2] = make_uint2(pbl[i][0], pbl[i][1]);
        }
    };

    // Two-pass compute: pass1 = Ah x (Bh, Bl); pass2 = Al x Bh.
    auto compute = [&](int buf) {
        const unsigned* Ah = smp + buf * 4096;
        const unsigned* Al = smp + buf * 4096 + 1024;
        const unsigned* Bh = smp + buf * 4096 + 2048;
        const unsigned* Bl = smp + buf * 4096 + 3072;
        uint4 af[4];
#pragma unroll
        for (int mt = 0; mt < 4; ++mt)
            af[mt] = *(const uint4*)&Ah[((warpM * 4 + mt) * 32 + lane) * 4];
#pragma unroll
        for (int nt = 0; nt < 4; ++nt) {
            int idx = (warpN * 4 + nt) * 32 + lane;
            uint2 bh = *(const uint2*)&Bh[idx * 2];
            uint2 bl = *(const uint2*)&Bl[idx * 2];
#pragma unroll
            for (int mt = 0; mt < 4; ++mt) {
                float* c = acc[mt][nt];
                mma_bf16(c[0], c[1], c[2], c[3],
                         af[mt].x, af[mt].y, af[mt].z, af[mt].w, bh.x, bh.y);
                mma_bf16(c[0], c[1], c[2], c[3],
                         af[mt].x, af[mt].y, af[mt].z, af[mt].w, bl.x, bl.y);
            }
        }
#pragma unroll
        for (int mt = 0; mt < 4; ++mt)
            af[mt] = *(const uint4*)&Al[((warpM * 4 + mt) * 32 + lane) * 4];
#pragma unroll
        for (int nt = 0; nt < 4; ++nt) {
            int idx = (warpN * 4 + nt) * 32 + lane;
            uint2 bh = *(const uint2*)&Bh[idx * 2];
#pragma unroll
            for (int mt = 0; mt < 4; ++mt) {
                float* c = acc[mt][nt];
                mma_bf16(c[0], c[1], c[2], c[3],
                         af[mt].x, af[mt].y, af[mt].z, af[mt].w, bh.x, bh.y);
            }
        }
    };

    const int kiters = K >> 4;
    loadG(0);
    storeS(0);
    __syncthreads();
    for (int it = 0; it < kiters; ++it) {
        const int cur = it & 1;
        if (it + 1 < kiters) loadG((it + 1) << 4);
        compute(cur);
        if (it + 1 < kiters) storeS(cur ^ 1);
        __syncthreads();
    }

    const int r = lane >> 2, j = lane & 3;
#pragma unroll
    for (int mt = 0; mt < 4; ++mt) {
        const int m0 = bm + warpM * 64 + mt * 16 + r;
        const float bv0 = bias ? bias[m0] : 0.f;
        const float bv1 = bias ? bias[m0 + 8] : 0.f;
#pragma unroll
        for (int nt = 0; nt < 4; ++nt) {
            const int n = bn + warpN * 32 + nt * 8 + j * 2;
            const float* c = acc[mt][nt];
            float r0 = alpha * c[0] + bv0, r1 = alpha * c[1] + bv0;
            float r2 = alpha * c[2] + bv1, r3 = alpha * c[3] + bv1;
            if (relu) {
                r0 = fmaxf(r0, 0.f); r1 = fmaxf(r1, 0.f);
                r2 = fmaxf(r2, 0.f); r3 = fmaxf(r3, 0.f);
            }
            *(float2*)&Cb[(size_t)m0 * N + n] = make_float2(r0, r1);
            *(float2*)&Cb[(size_t)(m0 + 8) * N + n] = make_float2(r2, r3);
        }
    }
}

__global__ __launch_bounds__(256, 2) void gemm_tc(
    const unsigned* __restrict__ Ahg, const unsigned* __restrict__ Alg,
    const unsigned* __restrict__ Bhg, const unsigned* __restrict__ Blg,
    float* __restrict__ C, int M, int K, int N,
    const float* __restrict__ bias, float alpha, int relu)
{
    extern __shared__ __align__(16) unsigned smp[];
    size_t bof = (size_t)blockIdx.z * (K >> 1) * N;
    gemm_body(Ahg, Alg, Bhg + bof, Blg + bof,
              C + (size_t)blockIdx.z * M * N, M, K, N, bias, alpha, relu, smp);
}

__global__ __launch_bounds__(256, 2) void gemm_qkv(
    const unsigned* __restrict__ wh, const unsigned* __restrict__ wl,
    const unsigned* __restrict__ lh, const unsigned* __restrict__ ll,
    const unsigned* __restrict__ rh, const unsigned* __restrict__ rl,
    float* ql, float* kl, float* vl, float* qr, float* kr, float* vr,
    float qscale)
{
    extern __shared__ __align__(16) unsigned smp[];
    const int z = blockIdx.z, which = z >> 1, b = z & 1;
    float* Cs[6] = {ql, kl, vl, qr, kr, vr};
    const unsigned* Ah = wh + (size_t)which * (EE * EE / 2);
    const unsigned* Al = wl + (size_t)which * (EE * EE / 2);
    const size_t bof = (size_t)b * (EE / 2) * SS;
    const unsigned* Bh = ((which < 3) ? lh : rh) + bof;
    const unsigned* Bl = ((which < 3) ? ll : rl) + bof;
    const float alpha = (which == 0 || which == 3) ? qscale : 1.f;
    gemm_body(Ah, Al, Bh, Bl, Cs[which] + (size_t)b * EE * SS,
              EE, EE, SS, nullptr, alpha, 0, smp);
}

// ---------------------------------------------------------------------------
// Tensor-core flash attention (unchanged from passing round 7/8)
// ---------------------------------------------------------------------------
#define ATTN_SMEM (16384 * 4)

__global__ __launch_bounds__(256, 2) void attn_mma(
    const float* __restrict__ Qlp, const float* __restrict__ Klp,
    const float* __restrict__ Vlp, float* __restrict__ Olp,
    const float* __restrict__ Qrp, const float* __restrict__ Krp,
    const float* __restrict__ Vrp, float* __restrict__ Orp)
{
    extern __shared__ __align__(16) unsigned smw[];
    unsigned* Qh = smw;            // 4096
    unsigned* Qlo = smw + 4096;    // 4096
    unsigned* Kh = smw + 8192;     // 2048
    unsigned* Klo = smw + 10240;   // 2048
    unsigned* Vh = smw + 12288;    // 2048
    unsigned* Vlo = smw + 14336;   // 2048

    const int tid = threadIdx.x;
    const int lane = tid & 31, w = tid >> 5;
    const int path = blockIdx.z >> 1;
    const int bz = blockIdx.z & 1;
    const float* Q = path ? Qrp : Qlp;
    const float* Kg = path ? Krp : Klp;
    const float* V = path ? Vrp : Vlp;
    float* O = path ? Orp : Olp;

    const int qt = (gridDim.x - 1) - blockIdx.x;
    const int q0 = qt << 7;
    const size_t base = ((size_t)bz * EE + (size_t)blockIdx.y * DD) * SS;
    const float* Qp = Q + base;
    const float* Kp = Kg + base;
    const float* Vp = V + base;

#pragma unroll
    for (int i = 0; i < 4; ++i) {
        int s = tid + (i << 8);
        int ls = s & 31, kc = (s >> 5) & 3, wq = s >> 7;
        int qr_ = q0 + (wq << 4) + (ls >> 2);
        int d0 = (kc << 4) + ((ls & 3) << 1);
        const float* p00 = Qp + (size_t)d0 * SS + qr_;
        float f0a = p00[0],              f0b = p00[SS];
        float f1a = p00[8],              f1b = p00[SS + 8];
        float f2a = p00[(size_t)8 * SS], f2b = p00[(size_t)9 * SS];
        float f3a = p00[(size_t)8 * SS + 8], f3b = p00[(size_t)9 * SS + 8];
        unsigned h0 = bf2pack(f0a, f0b), h1 = bf2pack(f1a, f1b);
        unsigned h2 = bf2pack(f2a, f2b), h3 = bf2pack(f3a, f3b);
        unsigned l0 = bf2pack(f0a - bfhi(f0a), f0b - bfhi(f0b));
        unsigned l1 = bf2pack(f1a - bfhi(f1a), f1b - bfhi(f1b));
        unsigned l2 = bf2pack(f2a - bfhi(f2a), f2b - bfhi(f2b));
        unsigned l3 = bf2pack(f3a - bfhi(f3a), f3b - bfhi(f3b));
        *(uint4*)&Qh[s * 4]  = make_uint4(h0, h1, h2, h3);
        *(uint4*)&Qlo[s * 4] = make_uint4(l0, l1, l2, l3);
    }

    float o[8][4];
#pragma unroll
    for (int i = 0; i < 8; ++i)
#pragma unroll
        for (int j = 0; j < 4; ++j) o[i][j] = 0.f;
    float m0 = -1e30f, m1 = -1e30f, l0s = 0.f, l1s = 0.f;

    const int qg = q0 + (w << 4) + (lane >> 2);
    const int ntile = qt * 2 + 2;

    for (int kt = 0; kt < ntile; ++kt) {
        const int t0 = kt << 6;
        __syncthreads();
#pragma unroll
        for (int i = 0; i < 4; ++i) {
            int s = tid + (i << 8);
            int ls = s & 31, kc = (s >> 5) & 3, nt = s >> 7;
            int tt = t0 + (nt << 3) + (ls >> 2);
            int d0 = (kc << 4) + ((ls & 3) << 1);
            const float* p00 = Kp + (size_t)d0 * SS + tt;
            float f0a = p00[0], f0b = p00[SS];
            float f1a = p00[(size_t)8 * SS], f1b = p00[(size_t)9 * SS];
            *(uint2*)&Kh[s * 2] = make_uint2(bf2pack(f0a, f0b), bf2pack(f1a, f1b));
            *(uint2*)&Klo[s * 2] = make_uint2(
                bf2pack(f0a - bfhi(f0a), f0b - bfhi(f0b)),
                bf2pack(f1a - bfhi(f1a), f1b - bfhi(f1b)));
        }
#pragma unroll
        for (int i = 0; i < 4; ++i) {
            int s = tid + (i << 8);
            int ls = s & 31, tc = (s >> 5) & 3, ndt = s >> 7;
            int d = (ndt << 3) + (ls >> 2);
            int tt = t0 + (tc << 4) + ((ls & 3) << 1);
            const float* p00 = Vp + (size_t)d * SS + tt;
            float2 v0 = *(const float2*)p00;
            float2 v1 = *(const float2*)(p00 + 8);
            *(uint2*)&Vh[s * 2] = make_uint2(bf2pack(v0.x, v0.y), bf2pack(v1.x, v1.y));
            *(uint2*)&Vlo[s * 2] = make_uint2(
                bf2pack(v0.x - bfhi(v0.x), v0.y - bfhi(v0.y)),
                bf2pack(v1.x - bfhi(v1.x), v1.y - bfhi(v1.y)));
        }
        __syncthreads();

        float sreg[8][4];
#pragma unroll
        for (int i = 0; i < 8; ++i)
#pragma unroll
            for (int j = 0; j < 4; ++j) sreg[i][j] = 0.f;
#pragma unroll
        for (int kc = 0; kc < 4; ++kc) {
            int ai = ((w * 4 + kc) * 32 + lane);
            uint4 ah = *(const uint4*)&Qh[ai * 4];
            uint4 al = *(const uint4*)&Qlo[ai * 4];
#pragma unroll
            for (int nt = 0; nt < 8; ++nt) {
                int bi = ((nt * 4 + kc) * 32 + lane);
                uint2 bh = *(const uint2*)&Kh[bi * 2];
                uint2 bl = *(const uint2*)&Klo[bi * 2];
                float* c = sreg[nt];
                mma_bf16(c[0], c[1], c[2], c[3], ah.x, ah.y, ah.z, ah.w, bh.x, bh.y);
                mma_bf16(c[0], c[1], c[2], c[3], ah.x, ah.y, ah.z, ah.w, bl.x, bl.y);
                mma_bf16(c[0], c[1], c[2], c[3], al.x, al.y, al.z, al.w, bh.x, bh.y);
            }
        }

        float mx0 = m0, mx1 = m1;
#pragma unroll
        for (int nt = 0; nt < 8; ++nt) {
            int tb = t0 + (nt << 3) + ((lane & 3) << 1);
            if (tb > qg)     sreg[nt][0] = -1e30f;
            if (tb + 1 > qg) sreg[nt][1] = -1e30f;
            if (tb > qg + 8)     sreg[nt][2] = -1e30f;
            if (tb + 1 > qg + 8) sreg[nt][3] = -1e30f;
            mx0 = fmaxf(mx0, fmaxf(sreg[nt][0], sreg[nt][1]));
            mx1 = fmaxf(mx1, fmaxf(sreg[nt][2], sreg[nt][3]));
        }
        mx0 = fmaxf(mx0, __shfl_xor_sync(0xffffffffu, mx0, 1));
        mx0 = fmaxf(mx0, __shfl_xor_sync(0xffffffffu, mx0, 2));
        mx1 = fmaxf(mx1, __shfl_xor_sync(0xffffffffu, mx1, 1));
        mx1 = fmaxf(mx1, __shfl_xor_sync(0xffffffffu, mx1, 2));
        float corr0 = exp2p(m0 - mx0), corr1 = exp2p(m1 - mx1);
        m0 = mx0; m1 = mx1;
        l0s *= corr0; l1s *= corr1;
#pragma unroll
        for (int nt = 0; nt < 8; ++nt) {
            o[nt][0] *= corr0; o[nt][1] *= corr0;
            o[nt][2] *= corr1; o[nt][3] *= corr1;
        }
        float ls0 = 0.f, ls1 = 0.f;
#pragma unroll
        for (int nt = 0; nt < 8; ++nt) {
            float p0 = exp2p(sreg[nt][0] - mx0);
            float p1 = exp2p(sreg[nt][1] - mx0);
            float p2 = exp2p(sreg[nt][2] - mx1);
            float p3 = exp2p(sreg[nt][3] - mx1);
            sreg[nt][0] = p0; sreg[nt][1] = p1;
            sreg[nt][2] = p2; sreg[nt][3] = p3;
            ls0 += p0 + p1; ls1 += p2 + p3;
        }
        ls0 += __shfl_xor_sync(0xffffffffu, ls0, 1);
        ls0 += __shfl_xor_sync(0xffffffffu, ls0, 2);
        ls1 += __shfl_xor_sync(0xffffffffu, ls1, 1);
        ls1 += __shfl_xor_sync(0xffffffffu, ls1, 2);
        l0s += ls0; l1s += ls1;

#pragma unroll
        for (int j = 0; j < 4; ++j) {
            float* pA = sreg[2 * j];
            float* pB = sreg[2 * j + 1];
            unsigned ah0 = bf2pack(pA[0], pA[1]);
            unsigned ah1 = bf2pack(pA[2], pA[3]);
            unsigned ah2 = bf2pack(pB[0], pB[1]);
            unsigned ah3 = bf2pack(pB[2], pB[3]);
            unsigned al0 = bf2pack(pA[0] - bfhi(pA[0]), pA[1] - bfhi(pA[1]));
            unsigned al1 = bf2pack(pA[2] - bfhi(pA[2]), pA[3] - bfhi(pA[3]));
            unsigned al2 = bf2pack(pB[0] - bfhi(pB[0]), pB[1] - bfhi(pB[1]));
            unsigned al3 = bf2pack(pB[2] - bfhi(pB[2]), pB[3] - bfhi(pB[3]));
#pragma unroll
            for (int nt = 0; nt < 8; ++nt) {
                int bi = ((nt * 4 + j) * 32 + lane);
                uint2 bh = *(const uint2*)&Vh[bi * 2];
                uint2 bl = *(const uint2*)&Vlo[bi * 2];
                float* c = o[nt];
                mma_bf16(c[0], c[1], c[2], c[3], ah0, ah1, ah2, ah3, bh.x, bh.y);
                mma_bf16(c[0], c[1], c[2], c[3], ah0, ah1, ah2, ah3, bl.x, bl.y);
                mma_bf16(c[0], c[1], c[2], c[3], al0, al1, al2, al3, bh.x, bh.y);
            }
        }
    }

    const float inv0 = 1.f / l0s, inv1 = 1.f / l1s;
    float* Op = O + base;
#pragma unroll
    for (int nt = 0; nt < 8; ++nt) {
        int d = (nt << 3) + ((lane & 3) << 1);
        Op[(size_t)d * SS + qg]       = o[nt][0] * inv0;
        Op[(size_t)(d + 1) * SS + qg] = o[nt][1] * inv0;
        Op[(size_t)d * SS + qg + 8]       = o[nt][2] * inv1;
        Op[(size_t)(d + 1) * SS + qg + 8] = o[nt][3] * inv1;
    }
}

// ---------------------------------------------------------------------------
// lambda = exp(sum lam_q_l*lam_k_l) - exp(sum lam_q_r*lam_k_r) + 0.1
// ---------------------------------------------------------------------------
__global__ void lam_kernel(const float* __restrict__ ql, const float* __restrict__ kl,
                           const float* __restrict__ qr, const float* __restrict__ kr)
{
    const int t = threadIdx.x;
    float a = ql[t] * kl[t] + ql[t + 32] * kl[t + 32];
    float b = qr[t] * kr[t] + qr[t + 32] * kr[t + 32];
#pragma unroll
    for (int off = 16; off > 0; off >>= 1) {
        a += __shfl_xor_sync(0xffffffffu, a, off);
        b += __shfl_xor_sync(0xffffffffu, b, off);
    }
    if (t == 0) g_lam = expf(a) - expf(b) + 0.1f;
}

// ---------------------------------------------------------------------------
// combined = attn_l - lam*attn_r; LayerNorm over E; output written directly
// as packed hi/lo bf16-pair planes (B-pack over e) for the next GEMM.
// ---------------------------------------------------------------------------
__global__ __launch_bounds__(512) void ln_kernel(
    const float* __restrict__ al, const float* __restrict__ ar,
    const float* __restrict__ gg, const float* __restrict__ bbv,
    unsigned* __restrict__ outh, unsigned* __restrict__ outl)
{
    __shared__ float ps[16][32], pq[16][32], smu[32], srs[32];
    const int tid = threadIdx.x;
    const int ty = tid >> 5, sl = tid & 31;
    const int b = blockIdx.x >> 6;
    const int s = ((blockIdx.x & 63) << 5) + sl;
    const float lam = g_lam;
    const size_t col = (size_t)b * EE * SS + s;
    const int e0 = ty << 6;

    float sum = 0.f, sq = 0.f;
    for (int e = e0; e < e0 + 64; ++e) {
        size_t idx = col + (size_t)e * SS;
        float c = al[idx] - lam * ar[idx];
        sum += c; sq += c * c;
    }
    ps[ty][sl] = sum; pq[ty][sl] = sq;
    __syncthreads();
    if (ty == 0) {
        float ts = 0.f, tq = 0.f;
#pragma unroll
        for (int r = 0; r < 16; ++r) { ts += ps[r][sl]; tq += pq[r][sl]; }
        float mu = ts * (1.f / EE);
        float var = tq * (1.f / EE) - mu * mu;
        smu[sl] = mu;
        srs[sl] = rsqrtf(var + 1e-5f);
    }
    __syncthreads();
    const float mu = smu[sl], rs = srs[sl];
    const size_t wbase = (size_t)b * (EE / 2) * SS + s;
    for (int e2 = e0 >> 1; e2 < (e0 >> 1) + 32; ++e2) {
        size_t i0 = col + (size_t)(2 * e2) * SS;
        size_t i1 = col + (size_t)(2 * e2 + 1) * SS;
        float c0 = al[i0] - lam * ar[i0];
        float c1 = al[i1] - lam * ar[i1];
        float y0 = (c0 - mu) * rs * gg[2 * e2] + bbv[2 * e2];
        float y1 = (c1 - mu) * rs * gg[2 * e2 + 1] + bbv[2 * e2 + 1];
        size_t w = wbase + (size_t)e2 * SS;
        outh[w] = bf2pack(y0, y1);
        outl[w] = bf2pack(y0 - bfhi(y0), y1 - bfhi(y1));
    }
}

// ---------------------------------------------------------------------------
// Launch
// ---------------------------------------------------------------------------
static void* sym_addr(const void* symbol)
{
    void* p = nullptr;
    cudaGetSymbolAddress(&p, symbol);
    return p;
}

extern "C" void kernel_launch(void* const* d_in, const int* in_sizes, int n_in,
                              void* d_out, int out_size)
{
    const float* left  = (const float*)d_in[0];
    const float* right = (const float*)d_in[1];
    const float* Wq_l  = (const float*)d_in[2];
    const float* Wk_l  = (const float*)d_in[3];
    const float* Wv_l  = (const float*)d_in[4];
    const float* Wq_r  = (const float*)d_in[5];
    const float* Wk_r  = (const float*)d_in[6];
    const float* Wv_r  = (const float*)d_in[7];
    const float* Wo    = (const float*)d_in[8];
    const float* lql   = (const float*)d_in[9];
    const float* lkl   = (const float*)d_in[10];
    const float* lqr   = (const float*)d_in[11];
    const float* lkr   = (const float*)d_in[12];
    const float* ln_g  = (const float*)d_in[13];
    const float* ln_b  = (const float*)d_in[14];
    const float* W1    = (const float*)d_in[15];
    const float* b1    = (const float*)d_in[16];
    const float* W2    = (const float*)d_in[17];
    const float* b2    = (const float*)d_in[18];
    float* out = (float*)d_out;

    float* ql = (float*)sym_addr(g_ql); float* kl = (float*)sym_addr(g_kl);
    float* vl = (float*)sym_addr(g_vl); float* qr = (float*)sym_addr(g_qr);
    float* kr = (float*)sym_addr(g_kr); float* vr = (float*)sym_addr(g_vr);
    float* al = (float*)sym_addr(g_al); float* ar = (float*)sym_addr(g_ar);
    float* h1 = (float*)sym_addr(g_h1); float* wf = (float*)sym_addr(g_wf);
    unsigned* lh = (unsigned*)sym_addr(g_lh); unsigned* ll = (unsigned*)sym_addr(g_ll);
    unsigned* rh = (unsigned*)sym_addr(g_rh); unsigned* rl = (unsigned*)sym_addr(g_rl);
    unsigned* wh = (unsigned*)sym_addr(g_wh); unsigned* wl = (unsigned*)sym_addr(g_wl);
    unsigned* w1h = (unsigned*)sym_addr(g_w1h); unsigned* w1l = (unsigned*)sym_addr(g_w1l);
    unsigned* w2h = (unsigned*)sym_addr(g_w2h); unsigned* w2l = (unsigned*)sym_addr(g_w2l);
    unsigned* woh = (unsigned*)sym_addr(g_woh); unsigned* wol = (unsigned*)sym_addr(g_wol);
    unsigned* wfh = (unsigned*)sym_addr(g_wfh); unsigned* wfl = (unsigned*)sym_addr(g_wfl);
    unsigned* lnh = (unsigned*)sym_addr(g_lnh); unsigned* lnl = (unsigned*)sym_addr(g_lnl);
    unsigned* h1h = (unsigned*)sym_addr(g_h1h); unsigned* h1l = (unsigned*)sym_addr(g_h1l);

    // D^-0.5 * log2(e): scores in log2 domain (softmax-invariant)
    const float qscale = 0.125f * 1.4426950408889634f;

    cudaFuncSetAttribute(gemm_tc, cudaFuncAttributeMaxDynamicSharedMemorySize,
                         GEMM_SMEM);
    cudaFuncSetAttribute(gemm_qkv, cudaFuncAttributeMaxDynamicSharedMemorySize,
                         GEMM_SMEM);
    cudaFuncSetAttribute(attn_mma, cudaFuncAttributeMaxDynamicSharedMemorySize,
                         ATTN_SMEM);

    const int WW2 = EE * EE / 2;   // words per E x E matrix

    // ---- pack weights (A-pack) and inputs/Wo (B-pack) ----
    pack_a<<<WW2 / 256, 256>>>(Wq_l, wh + 0 * WW2, wl + 0 * WW2, WW2);
    pack_a<<<WW2 / 256, 256>>>(Wk_l, wh + 1 * WW2, wl + 1 * WW2, WW2);
    pack_a<<<WW2 / 256, 256>>>(Wv_l, wh + 2 * WW2, wl + 2 * WW2, WW2);
    pack_a<<<WW2 / 256, 256>>>(Wq_r, wh + 3 * WW2, wl + 3 * WW2, WW2);
    pack_a<<<WW2 / 256, 256>>>(Wk_r, wh + 4 * WW2, wl + 4 * WW2, WW2);
    pack_a<<<WW2 / 256, 256>>>(Wv_r, wh + 5 * WW2, wl + 5 * WW2, WW2);
    pack_a<<<(EE * EE) / 256, 256>>>(W1, w1h, w1l, EE * EE);
    pack_a<<<(EE * EE) / 256, 256>>>(W2, w2h, w2l, EE * EE);
    pack_b<<<dim3(EE / 256, EE / 2), 256>>>(Wo, woh, wol, EE);
    pack_b<<<dim3(SS / 256, BB * EE / 2), 256>>>(left, lh, ll, SS);
    pack_b<<<dim3(SS / 256, BB * EE / 2), 256>>>(right, rh, rl, SS);

    // ---- wf = W1 @ Wo (precompute), then A-pack ----
    dim3 blk(256);
    gemm_tc<<<dim3(EE / 128, 2 * EE / 128, 1), blk, GEMM_SMEM>>>(
        w1h, w1l, woh, wol, wf, 2 * EE, EE, EE, nullptr, 1.f, 0);
    pack_a<<<(EE * EE) / 256, 256>>>(wf, wfh, wfl, EE * EE);

    // ---- QKV projections (one launch, packed operands) ----
    gemm_qkv<<<dim3(SS / 128, EE / 128, 6 * BB), blk, GEMM_SMEM>>>(
        wh, wl, lh, ll, rh, rl, ql, kl, vl, qr, kr, vr, qscale);

    // ---- attention (unchanged) ----
    attn_mma<<<dim3(SS / 128, HH, 2 * BB), 256, ATTN_SMEM>>>(
        ql, kl, vl, al, qr, kr, vr, ar);

    // ---- lambda, combine + LN (writes packed planes) ----
    lam_kernel<<<1, 32>>>(lql, lkl, lqr, lkr);
    ln_kernel<<<BB * (SS / 32), 512>>>(al, ar, ln_g, ln_b, lnh, lnl);

    // ---- h1 = relu(wf @ ln + b1); pack; out = W2 @ h1 + b2 ----
    gemm_tc<<<dim3(SS / 128, 2 * EE / 128, BB), blk, GEMM_SMEM>>>(
        wfh, wfl, lnh, lnl, h1, 2 * EE, EE, SS, b1, 1.f, 1);
    pack_b<<<dim3(SS / 256, BB * 2 * EE / 2), 256>>>(h1, h1h, h1l, SS);
    gemm_tc<<<dim3(SS / 128, EE / 128, BB), blk, GEMM_SMEM>>>(
        w2h, w2l, h1h, h1l, out, EE, 2 * EE, SS, b2, 1.f, 0);
}

// round 10
// speedup vs baseline: 1.0411x; 1.0411x over previous
#include <cuda_runtime.h>
#include <cuda_bf16.h>
#include <math.h>

// Problem constants
#define BB 2
#define EE 1024
#define SS 2048
#define HH 16
#define DD 64
#define BES (BB*EE*SS)          // 4,194,304 elements

// ---------------------------------------------------------------------------
// Scratch (device globals; no runtime allocation allowed)
// ---------------------------------------------------------------------------
__device__ float g_al[BES], g_ar[BES];
__device__ float g_lnout[BES];
__device__ float g_h1[2 * BES];
__device__ float g_wf[2 * EE * EE];
__device__ float g_lam;

// Packed hi/lo bf16-pair planes for attention inputs, written by QKV epilogue.
// q/k planes: [path][b][e2][s]  (pair along e/d axis), BES/2 words per path
// v planes:   [path][b][e][s2]  (pair along s axis),   BES/2 words per path
__device__ unsigned g_qh[BES], g_qlo[BES];
__device__ unsigned g_kh[BES], g_klo[BES];
__device__ unsigned g_vh[BES], g_vlo[BES];

// ---------------------------------------------------------------------------
// bf16 split helpers
// ---------------------------------------------------------------------------
__device__ __forceinline__ unsigned bf2pack(float x, float y) {
    __nv_bfloat162 h = __floats2bfloat162_rn(x, y);
    return *reinterpret_cast<unsigned*>(&h);
}
__device__ __forceinline__ float bfhi(float x) {
    return __bfloat162float(__float2bfloat16(x));
}
__device__ __forceinline__ void mma_bf16(
    float& c0, float& c1, float& c2, float& c3,
    unsigned a0, unsigned a1, unsigned a2, unsigned a3,
    unsigned b0, unsigned b1)
{
    asm("mma.sync.aligned.m16n8k16.row.col.f32.bf16.bf16.f32 "
        "{%0,%1,%2,%3}, {%4,%5,%6,%7}, {%8,%9}, {%0,%1,%2,%3};"
        : "+f"(c0), "+f"(c1), "+f"(c2), "+f"(c3)
        : "r"(a0), "r"(a1), "r"(a2), "r"(a3), "r"(b0), "r"(b1));
}

// exp2 via FMA-pipe polynomial (degree-5, rel ~2e-6) — dodges MUFU ceiling.
__device__ __forceinline__ float exp2p(float z) {
    z = fmaxf(z, -100.f);
    float n = rintf(z);
    float f = z - n;
    float p = 0.00133335581f;
    p = fmaf(p, f, 0.00961812911f);
    p = fmaf(p, f, 0.05550410866f);
    p = fmaf(p, f, 0.24022650696f);
    p = fmaf(p, f, 0.69314718056f);
    p = fmaf(p, f, 1.0f);
    float sc = __int_as_float(((int)n + 127) << 23);
    return p * sc;
}

// ---------------------------------------------------------------------------
// Tensor-core GEMM body (3-product split-bf16 m16n8k16), double-buffered,
// two-pass compute — round-8 verified loader/compute. Epilogue modes:
//   mode 0: fp32 C (+bias/relu)           mode 1: packed planes, pair over m
//   mode 2: packed planes, pair over n
// Per-buffer word layout: Ah[0..1023] Al[1024..2047] Bh[2048..3071] Bl[3072..4095]
// ---------------------------------------------------------------------------
#define GEMM_SMEM (2 * 4096 * 4)

__device__ __forceinline__ void gemm_body(
    const float* __restrict__ W, const float* __restrict__ Xb,
    float* __restrict__ Cb, unsigned* __restrict__ outh,
    unsigned* __restrict__ outl, int mode,
    int M, int K, int N, const float* __restrict__ bias, float alpha, int relu,
    unsigned* smp)
{
    const int t = threadIdx.x;
    const int lane = t & 31, wid = t >> 5;
    const int warpM = wid >> 2, warpN = wid & 3;
    const int bm = blockIdx.y << 7, bn = blockIdx.x << 7;

    float acc[4][4][4];
#pragma unroll
    for (int a = 0; a < 4; ++a)
#pragma unroll
        for (int b = 0; b < 4; ++b)
#pragma unroll
            for (int c = 0; c < 4; ++c) acc[a][b][c] = 0.f;

    const int amt = t >> 5, als = t & 31;
    const int amo = (amt << 4) + (als >> 2);
    const int ako = (als & 3) << 1;
    int bno[2], bko[2];
#pragma unroll
    for (int i = 0; i < 2; ++i) {
        int s = t + (i << 8), nt = s >> 5, ls = s & 31;
        bno[i] = (nt << 3) + (ls >> 2);
        bko[i] = (ls & 3) << 1;
    }

    float2 pa[4];
    float2 pb[2][2];

    auto loadG = [&](int k0) {
        const float* ap = W + (size_t)(bm + amo) * K + (k0 + ako);
        pa[0] = *(const float2*)ap;
        pa[1] = *(const float2*)(ap + (size_t)8 * K);
        pa[2] = *(const float2*)(ap + 8);
        pa[3] = *(const float2*)(ap + (size_t)8 * K + 8);
#pragma unroll
        for (int i = 0; i < 2; ++i) {
            const float* bp = Xb + (size_t)(k0 + bko[i]) * N + bn + bno[i];
            pb[i][0] = make_float2(bp[0], bp[N]);
            pb[i][1] = make_float2(bp[(size_t)8 * N], bp[(size_t)9 * N]);
        }
    };

    auto storeS = [&](int buf) {
        unsigned* Ah = smp + buf * 4096;
        unsigned* Al = smp + buf * 4096 + 1024;
        unsigned* Bh = smp + buf * 4096 + 2048;
        unsigned* Bl = smp + buf * 4096 + 3072;
        {
            unsigned h[4], l[4];
#pragma unroll
            for (int r = 0; r < 4; ++r) {
                float hx = bfhi(pa[r].x), hy = bfhi(pa[r].y);
                h[r] = bf2pack(pa[r].x, pa[r].y);
                l[r] = bf2pack(pa[r].x - hx, pa[r].y - hy);
            }
            *(uint4*)&Ah[t * 4] = make_uint4(h[0], h[1], h[2], h[3]);
            *(uint4*)&Al[t * 4] = make_uint4(l[0], l[1], l[2], l[3]);
        }
#pragma unroll
        for (int i = 0; i < 2; ++i) {
            int s = t + (i << 8);
            float hx = bfhi(pb[i][0].x), hy = bfhi(pb[i][0].y);
            unsigned h0 = bf2pack(pb[i][0].x, pb[i][0].y);
            unsigned l0 = bf2pack(pb[i][0].x - hx, pb[i][0].y - hy);
            hx = bfhi(pb[i][1].x); hy = bfhi(pb[i][1].y);
            unsigned h1 = bf2pack(pb[i][1].x, pb[i][1].y);
            unsigned l1 = bf2pack(pb[i][1].x - hx, pb[i][1].y - hy);
            *(uint2*)&Bh[s * 2] = make_uint2(h0, h1);
            *(uint2*)&Bl[s * 2] = make_uint2(l0, l1);
        }
    };

    auto compute = [&](int buf) {
        const unsigned* Ah = smp + buf * 4096;
        const unsigned* Al = smp + buf * 4096 + 1024;
        const unsigned* Bh = smp + buf * 4096 + 2048;
        const unsigned* Bl = smp + buf * 4096 + 3072;
        uint4 af[4];
#pragma unroll
        for (int mt = 0; mt < 4; ++mt)
            af[mt] = *(const uint4*)&Ah[((warpM * 4 + mt) * 32 + lane) * 4];
#pragma unroll
        for (int nt = 0; nt < 4; ++nt) {
            int idx = (warpN * 4 + nt) * 32 + lane;
            uint2 bh = *(const uint2*)&Bh[idx * 2];
            uint2 bl = *(const uint2*)&Bl[idx * 2];
#pragma unroll
            for (int mt = 0; mt < 4; ++mt) {
                float* c = acc[mt][nt];
                mma_bf16(c[0], c[1], c[2], c[3],
                         af[mt].x, af[mt].y, af[mt].z, af[mt].w, bh.x, bh.y);
                mma_bf16(c[0], c[1], c[2], c[3],
                         af[mt].x, af[mt].y, af[mt].z, af[mt].w, bl.x, bl.y);
            }
        }
#pragma unroll
        for (int mt = 0; mt < 4; ++mt)
            af[mt] = *(const uint4*)&Al[((warpM * 4 + mt) * 32 + lane) * 4];
#pragma unroll
        for (int nt = 0; nt < 4; ++nt) {
            int idx = (warpN * 4 + nt) * 32 + lane;
            uint2 bh = *(const uint2*)&Bh[idx * 2];
#pragma unroll
            for (int mt = 0; mt < 4; ++mt) {
                float* c = acc[mt][nt];
                mma_bf16(c[0], c[1], c[2], c[3],
                         af[mt].x, af[mt].y, af[mt].z, af[mt].w, bh.x, bh.y);
            }
        }
    };

    const int kiters = K >> 4;
    loadG(0);
    storeS(0);
    __syncthreads();
    for (int it = 0; it < kiters; ++it) {
        const int cur = it & 1;
        if (it + 1 < kiters) loadG((it + 1) << 4);
        compute(cur);
        if (it + 1 < kiters) storeS(cur ^ 1);
        __syncthreads();
    }

    // ---- epilogue ----
    const int r = lane >> 2, j = lane & 3;
#pragma unroll
    for (int mt = 0; mt < 4; ++mt) {
        const int m0 = bm + warpM * 64 + mt * 16 + r;
#pragma unroll
        for (int nt = 0; nt < 4; ++nt) {
            const int n = bn + warpN * 32 + nt * 8 + j * 2;
            const float* c = acc[mt][nt];
            float r0 = alpha * c[0], r1 = alpha * c[1];
            float r2 = alpha * c[2], r3 = alpha * c[3];
            if (mode == 0) {
                const float bv0 = bias ? bias[m0] : 0.f;
                const float bv1 = bias ? bias[m0 + 8] : 0.f;
                r0 += bv0; r1 += bv0; r2 += bv1; r3 += bv1;
                if (relu) {
                    r0 = fmaxf(r0, 0.f); r1 = fmaxf(r1, 0.f);
                    r2 = fmaxf(r2, 0.f); r3 = fmaxf(r3, 0.f);
                }
                *(float2*)&Cb[(size_t)m0 * N + n] = make_float2(r0, r1);
                *(float2*)&Cb[(size_t)(m0 + 8) * N + n] = make_float2(r2, r3);
            } else if (mode == 1) {
                // pair over m: exchange row-partner (m0 ^ 1) via lane^4
                float p0 = __shfl_xor_sync(0xffffffffu, r0, 4);
                float p1 = __shfl_xor_sync(0xffffffffu, r1, 4);
                float p2 = __shfl_xor_sync(0xffffffffu, r2, 4);
                float p3 = __shfl_xor_sync(0xffffffffu, r3, 4);
                if (!(lane & 4)) {   // even r: owns rows 2i; partner has 2i+1
                    size_t w0 = (size_t)(m0 >> 1) * N + n;
                    size_t w1 = (size_t)((m0 + 8) >> 1) * N + n;
                    outh[w0]     = bf2pack(r0, p0);
                    outh[w0 + 1] = bf2pack(r1, p1);
                    outh[w1]     = bf2pack(r2, p2);
                    outh[w1 + 1] = bf2pack(r3, p3);
                    outl[w0]     = bf2pack(r0 - bfhi(r0), p0 - bfhi(p0));
                    outl[w0 + 1] = bf2pack(r1 - bfhi(r1), p1 - bfhi(p1));
                    outl[w1]     = bf2pack(r2 - bfhi(r2), p2 - bfhi(p2));
                    outl[w1 + 1] = bf2pack(r3 - bfhi(r3), p3 - bfhi(p3));
                }
            } else {
                // pair over n: (n, n+1) already in this thread
                size_t w0 = (size_t)m0 * (N >> 1) + (n >> 1);
                size_t w1 = (size_t)(m0 + 8) * (N >> 1) + (n >> 1);
                outh[w0] = bf2pack(r0, r1);
                outh[w1] = bf2pack(r2, r3);
                outl[w0] = bf2pack(r0 - bfhi(r0), r1 - bfhi(r1));
                outl[w1] = bf2pack(r2 - bfhi(r2), r3 - bfhi(r3));
            }
        }
    }
}

__global__ __launch_bounds__(256, 2) void gemm_tc(
    const float* __restrict__ W, const float* __restrict__ X,
    float* __restrict__ C, int M, int K, int N,
    const float* __restrict__ bias, float alpha, int relu)
{
    extern __shared__ __align__(16) unsigned smp[];
    gemm_body(W, X + (size_t)blockIdx.z * K * N, C + (size_t)blockIdx.z * M * N,
              nullptr, nullptr, 0, M, K, N, bias, alpha, relu, smp);
}

// All 6 QKV projections, one launch, writing packed attention-ready planes.
// z = which*2 + b; which 0..5 = [q_l, k_l, v_l, q_r, k_r, v_r].
__global__ __launch_bounds__(256, 2) void gemm_qkv(
    const float* __restrict__ Wq_l, const float* __restrict__ Wk_l,
    const float* __restrict__ Wv_l, const float* __restrict__ Wq_r,
    const float* __restrict__ Wk_r, const float* __restrict__ Wv_r,
    const float* __restrict__ left, const float* __restrict__ right,
    float qscale)
{
    extern __shared__ __align__(16) unsigned smp[];
    const int z = blockIdx.z, which = z >> 1, b = z & 1;
    const int path = which / 3, kind = which % 3;
    const float* Ws[6] = {Wq_l, Wk_l, Wv_l, Wq_r, Wk_r, Wv_r};
    const float* X = path ? right : left;
    const float alpha = (kind == 0) ? qscale : 1.f;

    unsigned *outh, *outl;
    size_t off;
    int mode;
    if (kind == 2) {   // V: pair over n (s axis)
        mode = 2;
        off = (size_t)path * (BES / 2) + (size_t)b * EE * (SS / 2);
        outh = g_vh + off; outl = g_vlo + off;
    } else {           // Q/K: pair over m (e axis)
        mode = 1;
        off = (size_t)path * (BES / 2) + (size_t)b * (EE / 2) * SS;
        if (kind == 0) { outh = g_qh + off; outl = g_qlo + off; }
        else           { outh = g_kh + off; outl = g_klo + off; }
    }
    gemm_body(Ws[which], X + (size_t)b * EE * SS, nullptr, outh, outl, mode,
              EE, EE, SS, nullptr, alpha, 0, smp);
}

// ---------------------------------------------------------------------------
// Tensor-core flash attention — identical compute to the round-7/8 verified
// kernel; loaders now consume pre-packed planes (pure word loads, zero
// conversion math in the kt loop).
// ---------------------------------------------------------------------------
#define ATTN_SMEM (16384 * 4)

__global__ __launch_bounds__(256, 2) void attn_mma(
    float* __restrict__ Olp, float* __restrict__ Orp)
{
    extern __shared__ __align__(16) unsigned smw[];
    unsigned* Qh = smw;            // 4096
    unsigned* Qlo = smw + 4096;    // 4096
    unsigned* Kh = smw + 8192;     // 2048
    unsigned* Klo = smw + 10240;   // 2048
    unsigned* Vh = smw + 12288;    // 2048
    unsigned* Vlo = smw + 14336;   // 2048

    const int tid = threadIdx.x;
    const int lane = tid & 31, w = tid >> 5;
    const int path = blockIdx.z >> 1;
    const int bz = blockIdx.z & 1;
    float* O = path ? Orp : Olp;

    const int qt = (gridDim.x - 1) - blockIdx.x;   // heavy tiles first
    const int q0 = qt << 7;
    const size_t poff = (size_t)path * (BES / 2);
    const size_t base2 = poff + ((size_t)bz * (EE / 2) + (size_t)blockIdx.y * 32) * SS;
    const size_t baseV = poff + ((size_t)bz * EE + (size_t)blockIdx.y * DD) * (SS / 2);
    const size_t baseO = ((size_t)bz * EE + (size_t)blockIdx.y * DD) * SS;

    // ---- Q fragments (once per block): pure word loads from packed planes ----
#pragma unroll
    for (int i = 0; i < 4; ++i) {
        int s = tid + (i << 8);
        int ls = s & 31, kc = (s >> 5) & 3, wq = s >> 7;
        int qr_ = q0 + (wq << 4) + (ls >> 2);
        int e2 = (kc << 3) + (ls & 3);
        const unsigned* ph = g_qh + base2 + (size_t)e2 * SS;
        const unsigned* pl = g_qlo + base2 + (size_t)e2 * SS;
        *(uint4*)&Qh[s * 4] = make_uint4(ph[qr_], ph[qr_ + 8],
                                         ph[(size_t)4 * SS + qr_],
                                         ph[(size_t)4 * SS + qr_ + 8]);
        *(uint4*)&Qlo[s * 4] = make_uint4(pl[qr_], pl[qr_ + 8],
                                          pl[(size_t)4 * SS + qr_],
                                          pl[(size_t)4 * SS + qr_ + 8]);
    }

    float o[8][4];
#pragma unroll
    for (int i = 0; i < 8; ++i)
#pragma unroll
        for (int j = 0; j < 4; ++j) o[i][j] = 0.f;
    float m0 = -1e30f, m1 = -1e30f, l0s = 0.f, l1s = 0.f;

    const int qg = q0 + (w << 4) + (lane >> 2);
    const int ntile = qt * 2 + 2;

    for (int kt = 0; kt < ntile; ++kt) {
        const int t0 = kt << 6;
        __syncthreads();
        // K fragments: 2 word loads per plane per slot
#pragma unroll
        for (int i = 0; i < 4; ++i) {
            int s = tid + (i << 8);
            int ls = s & 31, kc = (s >> 5) & 3, nt = s >> 7;
            int tt = t0 + (nt << 3) + (ls >> 2);
            int e2 = (kc << 3) + (ls & 3);
            const unsigned* ph = g_kh + base2 + (size_t)e2 * SS;
            const unsigned* pl = g_klo + base2 + (size_t)e2 * SS;
            *(uint2*)&Kh[s * 2] = make_uint2(ph[tt], ph[(size_t)4 * SS + tt]);
            *(uint2*)&Klo[s * 2] = make_uint2(pl[tt], pl[(size_t)4 * SS + tt]);
        }
        // V fragments: 2 word loads per plane per slot
#pragma unroll
        for (int i = 0; i < 4; ++i) {
            int s = tid + (i << 8);
            int ls = s & 31, tc = (s >> 5) & 3, ndt = s >> 7;
            int d = (ndt << 3) + (ls >> 2);
            int t2 = (t0 >> 1) + (tc << 3) + (ls & 3);
            const unsigned* ph = g_vh + baseV + (size_t)d * (SS / 2);
            const unsigned* pl = g_vlo + baseV + (size_t)d * (SS / 2);
            *(uint2*)&Vh[s * 2] = make_uint2(ph[t2], ph[t2 + 4]);
            *(uint2*)&Vlo[s * 2] = make_uint2(pl[t2], pl[t2 + 4]);
        }
        __syncthreads();

        float sreg[8][4];
#pragma unroll
        for (int i = 0; i < 8; ++i)
#pragma unroll
            for (int j = 0; j < 4; ++j) sreg[i][j] = 0.f;
#pragma unroll
        for (int kc = 0; kc < 4; ++kc) {
            int ai = ((w * 4 + kc) * 32 + lane);
            uint4 ah = *(const uint4*)&Qh[ai * 4];
            uint4 al = *(const uint4*)&Qlo[ai * 4];
#pragma unroll
            for (int nt = 0; nt < 8; ++nt) {
                int bi = ((nt * 4 + kc) * 32 + lane);
                uint2 bh = *(const uint2*)&Kh[bi * 2];
                uint2 bl = *(const uint2*)&Klo[bi * 2];
                float* c = sreg[nt];
                mma_bf16(c[0], c[1], c[2], c[3], ah.x, ah.y, ah.z, ah.w, bh.x, bh.y);
                mma_bf16(c[0], c[1], c[2], c[3], ah.x, ah.y, ah.z, ah.w, bl.x, bl.y);
                mma_bf16(c[0], c[1], c[2], c[3], al.x, al.y, al.z, al.w, bh.x, bh.y);
            }
        }

        float mx0 = m0, mx1 = m1;
#pragma unroll
        for (int nt = 0; nt < 8; ++nt) {
            int tb = t0 + (nt << 3) + ((lane & 3) << 1);
            if (tb > qg)     sreg[nt][0] = -1e30f;
            if (tb + 1 > qg) sreg[nt][1] = -1e30f;
            if (tb > qg + 8)     sreg[nt][2] = -1e30f;
            if (tb + 1 > qg + 8) sreg[nt][3] = -1e30f;
            mx0 = fmaxf(mx0, fmaxf(sreg[nt][0], sreg[nt][1]));
            mx1 = fmaxf(mx1, fmaxf(sreg[nt][2], sreg[nt][3]));
        }
        mx0 = fmaxf(mx0, __shfl_xor_sync(0xffffffffu, mx0, 1));
        mx0 = fmaxf(mx0, __shfl_xor_sync(0xffffffffu, mx0, 2));
        mx1 = fmaxf(mx1, __shfl_xor_sync(0xffffffffu, mx1, 1));
        mx1 = fmaxf(mx1, __shfl_xor_sync(0xffffffffu, mx1, 2));
        float corr0 = exp2p(m0 - mx0), corr1 = exp2p(m1 - mx1);
        m0 = mx0; m1 = mx1;
        l0s *= corr0; l1s *= corr1;
#pragma unroll
        for (int nt = 0; nt < 8; ++nt) {
            o[nt][0] *= corr0; o[nt][1] *= corr0;
            o[nt][2] *= corr1; o[nt][3] *= corr1;
        }
        float ls0 = 0.f, ls1 = 0.f;
#pragma unroll
        for (int nt = 0; nt < 8; ++nt) {
            float p0 = exp2p(sreg[nt][0] - mx0);
            float p1 = exp2p(sreg[nt][1] - mx0);
            float p2 = exp2p(sreg[nt][2] - mx1);
            float p3 = exp2p(sreg[nt][3] - mx1);
            sreg[nt][0] = p0; sreg[nt][1] = p1;
            sreg[nt][2] = p2; sreg[nt][3] = p3;
            ls0 += p0 + p1; ls1 += p2 + p3;
        }
        ls0 += __shfl_xor_sync(0xffffffffu, ls0, 1);
        ls0 += __shfl_xor_sync(0xffffffffu, ls0, 2);
        ls1 += __shfl_xor_sync(0xffffffffu, ls1, 1);
        ls1 += __shfl_xor_sync(0xffffffffu, ls1, 2);
        l0s += ls0; l1s += ls1;

#pragma unroll
        for (int j = 0; j < 4; ++j) {
            float* pA = sreg[2 * j];
            float* pB = sreg[2 * j + 1];
            unsigned ah0 = bf2pack(pA[0], pA[1]);
            unsigned ah1 = bf2pack(pA[2], pA[3]);
            unsigned ah2 = bf2pack(pB[0], pB[1]);
            unsigned ah3 = bf2pack(pB[2], pB[3]);
            unsigned al0 = bf2pack(pA[0] - bfhi(pA[0]), pA[1] - bfhi(pA[1]));
            unsigned al1 = bf2pack(pA[2] - bfhi(pA[2]), pA[3] - bfhi(pA[3]));
            unsigned al2 = bf2pack(pB[0] - bfhi(pB[0]), pB[1] - bfhi(pB[1]));
            unsigned al3 = bf2pack(pB[2] - bfhi(pB[2]), pB[3] - bfhi(pB[3]));
#pragma unroll
            for (int nt = 0; nt < 8; ++nt) {
                int bi = ((nt * 4 + j) * 32 + lane);
                uint2 bh = *(const uint2*)&Vh[bi * 2];
                uint2 bl = *(const uint2*)&Vlo[bi * 2];
                float* c = o[nt];
                mma_bf16(c[0], c[1], c[2], c[3], ah0, ah1, ah2, ah3, bh.x, bh.y);
                mma_bf16(c[0], c[1], c[2], c[3], ah0, ah1, ah2, ah3, bl.x, bl.y);
                mma_bf16(c[0], c[1], c[2], c[3], al0, al1, al2, al3, bh.x, bh.y);
            }
        }
    }

    const float inv0 = 1.f / l0s, inv1 = 1.f / l1s;
    float* Op = O + baseO;
#pragma unroll
    for (int nt = 0; nt < 8; ++nt) {
        int d = (nt << 3) + ((lane & 3) << 1);
        Op[(size_t)d * SS + qg]       = o[nt][0] * inv0;
        Op[(size_t)(d + 1) * SS + qg] = o[nt][1] * inv0;
        Op[(size_t)d * SS + qg + 8]       = o[nt][2] * inv1;
        Op[(size_t)(d + 1) * SS + qg + 8] = o[nt][3] * inv1;
    }
}

// ---------------------------------------------------------------------------
// lambda = exp(sum lam_q_l*lam_k_l) - exp(sum lam_q_r*lam_k_r) + 0.1
// ---------------------------------------------------------------------------
__global__ void lam_kernel(const float* __restrict__ ql, const float* __restrict__ kl,
                           const float* __restrict__ qr, const float* __restrict__ kr)
{
    const int t = threadIdx.x;
    float a = ql[t] * kl[t] + ql[t + 32] * kl[t + 32];
    float b = qr[t] * kr[t] + qr[t + 32] * kr[t + 32];
#pragma unroll
    for (int off = 16; off > 0; off >>= 1) {
        a += __shfl_xor_sync(0xffffffffu, a, off);
        b += __shfl_xor_sync(0xffffffffu, b, off);
    }
    if (t == 0) g_lam = expf(a) - expf(b) + 0.1f;
}

// ---------------------------------------------------------------------------
// combined = attn_l - lam*attn_r; LayerNorm over E (biased var, eps 1e-5).
// ---------------------------------------------------------------------------
__global__ __launch_bounds__(512) void ln_kernel(
    const float* __restrict__ al, const float* __restrict__ ar,
    const float* __restrict__ gg, const float* __restrict__ bbv,
    float* __restrict__ out)
{
    __shared__ float ps[16][32], pq[16][32], smu[32], srs[32];
    const int tid = threadIdx.x;
    const int ty = tid >> 5, sl = tid & 31;
    const int b = blockIdx.x >> 6;
    const int s = ((blockIdx.x & 63) << 5) + sl;
    const float lam = g_lam;
    const size_t col = (size_t)b * EE * SS + s;
    const int e0 = ty << 6;

    float sum = 0.f, sq = 0.f;
    for (int e = e0; e < e0 + 64; ++e) {
        size_t idx = col + (size_t)e * SS;
        float c = al[idx] - lam * ar[idx];
        sum += c; sq += c * c;
    }
    ps[ty][sl] = sum; pq[ty][sl] = sq;
    __syncthreads();
    if (ty == 0) {
        float ts = 0.f, tq = 0.f;
#pragma unroll
        for (int r = 0; r < 16; ++r) { ts += ps[r][sl]; tq += pq[r][sl]; }
        float mu = ts * (1.f / EE);
        float var = tq * (1.f / EE) - mu * mu;
        smu[sl] = mu;
        srs[sl] = rsqrtf(var + 1e-5f);
    }
    __syncthreads();
    const float mu = smu[sl], rs = srs[sl];
    for (int e = e0; e < e0 + 64; ++e) {
        size_t idx = col + (size_t)e * SS;
        float c = al[idx] - lam * ar[idx];
        out[idx] = (c - mu) * rs * gg[e] + bbv[e];
    }
}

// ---------------------------------------------------------------------------
// Launch
// ---------------------------------------------------------------------------
static float* sym_addr(const void* symbol)
{
    void* p = nullptr;
    cudaGetSymbolAddress(&p, symbol);
    return (float*)p;
}

extern "C" void kernel_launch(void* const* d_in, const int* in_sizes, int n_in,
                              void* d_out, int out_size)
{
    const float* left  = (const float*)d_in[0];
    const float* right = (const float*)d_in[1];
    const float* Wq_l  = (const float*)d_in[2];
    const float* Wk_l  = (const float*)d_in[3];
    const float* Wv_l  = (const float*)d_in[4];
    const float* Wq_r  = (const float*)d_in[5];
    const float* Wk_r  = (const float*)d_in[6];
    const float* Wv_r  = (const float*)d_in[7];
    const float* Wo    = (const float*)d_in[8];
    const float* lql   = (const float*)d_in[9];
    const float* lkl   = (const float*)d_in[10];
    const float* lqr   = (const float*)d_in[11];
    const float* lkr   = (const float*)d_in[12];
    const float* ln_g  = (const float*)d_in[13];
    const float* ln_b  = (const float*)d_in[14];
    const float* W1    = (const float*)d_in[15];
    const float* b1    = (const float*)d_in[16];
    const float* W2    = (const float*)d_in[17];
    const float* b2    = (const float*)d_in[18];
    float* out = (float*)d_out;

    float* al = sym_addr(g_al); float* ar = sym_addr(g_ar);
    float* lno = sym_addr(g_lnout);
    float* h1 = sym_addr(g_h1);
    float* wf = sym_addr(g_wf);

    // D^-0.5 * log2(e): scores in log2 domain (softmax-invariant)
    const float qscale = 0.125f * 1.4426950408889634f;

    cudaFuncSetAttribute(gemm_tc, cudaFuncAttributeMaxDynamicSharedMemorySize,
                         GEMM_SMEM);
    cudaFuncSetAttribute(gemm_qkv, cudaFuncAttributeMaxDynamicSharedMemorySize,
                         GEMM_SMEM);
    cudaFuncSetAttribute(attn_mma, cudaFuncAttributeMaxDynamicSharedMemorySize,
                         ATTN_SMEM);

    dim3 blk(256);

    // Wf = W1 @ Wo precompute (independent of activations)
    gemm_tc<<<dim3(EE / 128, 2 * EE / 128, 1), blk, GEMM_SMEM>>>(
        W1, Wo, wf, 2 * EE, EE, EE, nullptr, 1.f, 0);

    // QKV projections: one launch, epilogue writes packed attention planes
    gemm_qkv<<<dim3(SS / 128, EE / 128, 6 * BB), blk, GEMM_SMEM>>>(
        Wq_l, Wk_l, Wv_l, Wq_r, Wk_r, Wv_r, left, right, qscale);

    // attention: both paths in one launch (z = path*2 + b)
    attn_mma<<<dim3(SS / 128, HH, 2 * BB), 256, ATTN_SMEM>>>(al, ar);

    // lambda, combine + LN
    lam_kernel<<<1, 32>>>(lql, lkl, lqr, lkr);
    ln_kernel<<<BB * (SS / 32), 512>>>(al, ar, ln_g, ln_b, lno);

    // fused (W1@Wo) + relu, then W2 straight into d_out ([B,E,S])
    gemm_tc<<<dim3(SS / 128, 2 * EE / 128, BB), blk, GEMM_SMEM>>>(
        wf, lno, h1, 2 * EE, EE, SS, b1, 1.f, 1);
    gemm_tc<<<dim3(SS / 128, EE / 128, BB), blk, GEMM_SMEM>>>(
        W2, h1, out, EE, 2 * EE, SS, b2, 1.f, 0);
}

// round 11
// speedup vs baseline: 1.0434x; 1.0022x over previous
#include <cuda_runtime.h>
#include <cuda_bf16.h>
#include <math.h>

// Problem constants
#define BB 2
#define EE 1024
#define SS 2048
#define HH 16
#define DD 64
#define BES (BB*EE*SS)          // 4,194,304 elements

// ---------------------------------------------------------------------------
// Scratch (device globals; no runtime allocation allowed)
// ---------------------------------------------------------------------------
__device__ float g_al[BES], g_ar[BES];
__device__ float g_lnout[BES];
__device__ float g_h1[2 * BES];
__device__ float g_wf[2 * EE * EE];
__device__ float g_lam;

// Packed hi/lo bf16-pair planes for attention inputs, written by QKV epilogue.
// q/k planes: [path][b][e2][s]  (pair along e/d axis), BES/2 words per path
// v planes:   [path][b][e][s2]  (pair along s axis),   BES/2 words per path
__device__ unsigned g_qh[BES], g_qlo[BES];
__device__ unsigned g_kh[BES], g_klo[BES];
__device__ unsigned g_vh[BES], g_vlo[BES];

// ---------------------------------------------------------------------------
// bf16 split helpers
// ---------------------------------------------------------------------------
__device__ __forceinline__ unsigned bf2pack(float x, float y) {
    __nv_bfloat162 h = __floats2bfloat162_rn(x, y);
    return *reinterpret_cast<unsigned*>(&h);
}
__device__ __forceinline__ float bfhi(float x) {
    return __bfloat162float(__float2bfloat16(x));
}
__device__ __forceinline__ void mma_bf16(
    float& c0, float& c1, float& c2, float& c3,
    unsigned a0, unsigned a1, unsigned a2, unsigned a3,
    unsigned b0, unsigned b1)
{
    asm("mma.sync.aligned.m16n8k16.row.col.f32.bf16.bf16.f32 "
        "{%0,%1,%2,%3}, {%4,%5,%6,%7}, {%8,%9}, {%0,%1,%2,%3};"
        : "+f"(c0), "+f"(c1), "+f"(c2), "+f"(c3)
        : "r"(a0), "r"(a1), "r"(a2), "r"(a3), "r"(b0), "r"(b1));
}

// cp.async 4-byte word copy (zero-register global->SMEM)
__device__ __forceinline__ void cpa4(unsigned saddr, const void* gptr) {
    asm volatile("cp.async.ca.shared.global [%0], [%1], 4;"
                 :: "r"(saddr), "l"(gptr));
}

// exp2 via FMA-pipe polynomial (degree-5, rel ~2e-6) — dodges MUFU ceiling.
__device__ __forceinline__ float exp2p(float z) {
    z = fmaxf(z, -100.f);
    float n = rintf(z);
    float f = z - n;
    float p = 0.00133335581f;
    p = fmaf(p, f, 0.00961812911f);
    p = fmaf(p, f, 0.05550410866f);
    p = fmaf(p, f, 0.24022650696f);
    p = fmaf(p, f, 0.69314718056f);
    p = fmaf(p, f, 1.0f);
    float sc = __int_as_float(((int)n + 127) << 23);
    return p * sc;
}

// ---------------------------------------------------------------------------
// Tensor-core GEMM body (3-product split-bf16 m16n8k16), double-buffered,
// two-pass compute. Epilogue modes:
//   mode 0: fp32 C (+bias/relu)   mode 1: packed planes, pair over m
//   mode 2: packed planes, pair over n
// Per-buffer word layout: Ah[0..1023] Al[1024..2047] Bh[2048..3071] Bl[3072..4095]
// ---------------------------------------------------------------------------
#define GEMM_SMEM (2 * 4096 * 4)

__device__ __forceinline__ void gemm_body(
    const float* __restrict__ W, const float* __restrict__ Xb,
    float* __restrict__ Cb, unsigned* __restrict__ outh,
    unsigned* __restrict__ outl, int mode, int bm, int bn,
    int M, int K, int N, const float* __restrict__ bias, float alpha, int relu,
    unsigned* smp)
{
    const int t = threadIdx.x;
    const int lane = t & 31, wid = t >> 5;
    const int warpM = wid >> 2, warpN = wid & 3;

    float acc[4][4][4];
#pragma unroll
    for (int a = 0; a < 4; ++a)
#pragma unroll
        for (int b = 0; b < 4; ++b)
#pragma unroll
            for (int c = 0; c < 4; ++c) acc[a][b][c] = 0.f;

    const int amt = t >> 5, als = t & 31;
    const int amo = (amt << 4) + (als >> 2);
    const int ako = (als & 3) << 1;
    int bno[2], bko[2];
#pragma unroll
    for (int i = 0; i < 2; ++i) {
        int s = t + (i << 8), nt = s >> 5, ls = s & 31;
        bno[i] = (nt << 3) + (ls >> 2);
        bko[i] = (ls & 3) << 1;
    }

    float2 pa[4];
    float2 pb[2][2];

    auto loadG = [&](int k0) {
        const float* ap = W + (size_t)(bm + amo) * K + (k0 + ako);
        pa[0] = *(const float2*)ap;
        pa[1] = *(const float2*)(ap + (size_t)8 * K);
        pa[2] = *(const float2*)(ap + 8);
        pa[3] = *(const float2*)(ap + (size_t)8 * K + 8);
#pragma unroll
        for (int i = 0; i < 2; ++i) {
            const float* bp = Xb + (size_t)(k0 + bko[i]) * N + bn + bno[i];
            pb[i][0] = make_float2(bp[0], bp[N]);
            pb[i][1] = make_float2(bp[(size_t)8 * N], bp[(size_t)9 * N]);
        }
    };

    auto storeS = [&](int buf) {
        unsigned* Ah = smp + buf * 4096;
        unsigned* Al = smp + buf * 4096 + 1024;
        unsigned* Bh = smp + buf * 4096 + 2048;
        unsigned* Bl = smp + buf * 4096 + 3072;
        {
            unsigned h[4], l[4];
#pragma unroll
            for (int r = 0; r < 4; ++r) {
                float hx = bfhi(pa[r].x), hy = bfhi(pa[r].y);
                h[r] = bf2pack(pa[r].x, pa[r].y);
                l[r] = bf2pack(pa[r].x - hx, pa[r].y - hy);
            }
            *(uint4*)&Ah[t * 4] = make_uint4(h[0], h[1], h[2], h[3]);
            *(uint4*)&Al[t * 4] = make_uint4(l[0], l[1], l[2], l[3]);
        }
#pragma unroll
        for (int i = 0; i < 2; ++i) {
            int s = t + (i << 8);
            float hx = bfhi(pb[i][0].x), hy = bfhi(pb[i][0].y);
            unsigned h0 = bf2pack(pb[i][0].x, pb[i][0].y);
            unsigned l0 = bf2pack(pb[i][0].x - hx, pb[i][0].y - hy);
            hx = bfhi(pb[i][1].x); hy = bfhi(pb[i][1].y);
            unsigned h1 = bf2pack(pb[i][1].x, pb[i][1].y);
            unsigned l1 = bf2pack(pb[i][1].x - hx, pb[i][1].y - hy);
            *(uint2*)&Bh[s * 2] = make_uint2(h0, h1);
            *(uint2*)&Bl[s * 2] = make_uint2(l0, l1);
        }
    };

    auto compute = [&](int buf) {
        const unsigned* Ah = smp + buf * 4096;
        const unsigned* Al = smp + buf * 4096 + 1024;
        const unsigned* Bh = smp + buf * 4096 + 2048;
        const unsigned* Bl = smp + buf * 4096 + 3072;
        uint4 af[4];
#pragma unroll
        for (int mt = 0; mt < 4; ++mt)
            af[mt] = *(const uint4*)&Ah[((warpM * 4 + mt) * 32 + lane) * 4];
#pragma unroll
        for (int nt = 0; nt < 4; ++nt) {
            int idx = (warpN * 4 + nt) * 32 + lane;
            uint2 bh = *(const uint2*)&Bh[idx * 2];
            uint2 bl = *(const uint2*)&Bl[idx * 2];
#pragma unroll
            for (int mt = 0; mt < 4; ++mt) {
                float* c = acc[mt][nt];
                mma_bf16(c[0], c[1], c[2], c[3],
                         af[mt].x, af[mt].y, af[mt].z, af[mt].w, bh.x, bh.y);
                mma_bf16(c[0], c[1], c[2], c[3],
                         af[mt].x, af[mt].y, af[mt].z, af[mt].w, bl.x, bl.y);
            }
        }
#pragma unroll
        for (int mt = 0; mt < 4; ++mt)
            af[mt] = *(const uint4*)&Al[((warpM * 4 + mt) * 32 + lane) * 4];
#pragma unroll
        for (int nt = 0; nt < 4; ++nt) {
            int idx = (warpN * 4 + nt) * 32 + lane;
            uint2 bh = *(const uint2*)&Bh[idx * 2];
#pragma unroll
            for (int mt = 0; mt < 4; ++mt) {
                float* c = acc[mt][nt];
                mma_bf16(c[0], c[1], c[2], c[3],
                         af[mt].x, af[mt].y, af[mt].z, af[mt].w, bh.x, bh.y);
            }
        }
    };

    const int kiters = K >> 4;
    loadG(0);
    storeS(0);
    __syncthreads();
    for (int it = 0; it < kiters; ++it) {
        const int cur = it & 1;
        if (it + 1 < kiters) loadG((it + 1) << 4);
        compute(cur);
        if (it + 1 < kiters) storeS(cur ^ 1);
        __syncthreads();
    }

    // ---- epilogue ----
    const int r = lane >> 2, j = lane & 3;
#pragma unroll
    for (int mt = 0; mt < 4; ++mt) {
        const int m0 = bm + warpM * 64 + mt * 16 + r;
#pragma unroll
        for (int nt = 0; nt < 4; ++nt) {
            const int n = bn + warpN * 32 + nt * 8 + j * 2;
            const float* c = acc[mt][nt];
            float r0 = alpha * c[0], r1 = alpha * c[1];
            float r2 = alpha * c[2], r3 = alpha * c[3];
            if (mode == 0) {
                const float bv0 = bias ? bias[m0] : 0.f;
                const float bv1 = bias ? bias[m0 + 8] : 0.f;
                r0 += bv0; r1 += bv0; r2 += bv1; r3 += bv1;
                if (relu) {
                    r0 = fmaxf(r0, 0.f); r1 = fmaxf(r1, 0.f);
                    r2 = fmaxf(r2, 0.f); r3 = fmaxf(r3, 0.f);
                }
                *(float2*)&Cb[(size_t)m0 * N + n] = make_float2(r0, r1);
                *(float2*)&Cb[(size_t)(m0 + 8) * N + n] = make_float2(r2, r3);
            } else if (mode == 1) {
                float p0 = __shfl_xor_sync(0xffffffffu, r0, 4);
                float p1 = __shfl_xor_sync(0xffffffffu, r1, 4);
                float p2 = __shfl_xor_sync(0xffffffffu, r2, 4);
                float p3 = __shfl_xor_sync(0xffffffffu, r3, 4);
                if (!(lane & 4)) {
                    size_t w0 = (size_t)(m0 >> 1) * N + n;
                    size_t w1 = (size_t)((m0 + 8) >> 1) * N + n;
                    outh[w0]     = bf2pack(r0, p0);
                    outh[w0 + 1] = bf2pack(r1, p1);
                    outh[w1]     = bf2pack(r2, p2);
                    outh[w1 + 1] = bf2pack(r3, p3);
                    outl[w0]     = bf2pack(r0 - bfhi(r0), p0 - bfhi(p0));
                    outl[w0 + 1] = bf2pack(r1 - bfhi(r1), p1 - bfhi(p1));
                    outl[w1]     = bf2pack(r2 - bfhi(r2), p2 - bfhi(p2));
                    outl[w1 + 1] = bf2pack(r3 - bfhi(r3), p3 - bfhi(p3));
                }
            } else {
                size_t w0 = (size_t)m0 * (N >> 1) + (n >> 1);
                size_t w1 = (size_t)(m0 + 8) * (N >> 1) + (n >> 1);
                outh[w0] = bf2pack(r0, r1);
                outh[w1] = bf2pack(r2, r3);
                outl[w0] = bf2pack(r0 - bfhi(r0), r1 - bfhi(r1));
                outl[w1] = bf2pack(r2 - bfhi(r2), r3 - bfhi(r3));
            }
        }
    }
}

__global__ __launch_bounds__(256, 2) void gemm_tc(
    const float* __restrict__ W, const float* __restrict__ X,
    float* __restrict__ C, int M, int K, int N,
    const float* __restrict__ bias, float alpha, int relu)
{
    extern __shared__ __align__(16) unsigned smp[];
    gemm_body(W, X + (size_t)blockIdx.z * K * N, C + (size_t)blockIdx.z * M * N,
              nullptr, nullptr, 0, blockIdx.y << 7, blockIdx.x << 7,
              M, K, N, bias, alpha, relu, smp);
}

// QKV projections (z 0..11, packed-plane epilogues) + Wf=W1@Wo (z==12, 128
// tiles remapped onto the 16x8 xy slots) in ONE launch — Wf rides along free.
__global__ __launch_bounds__(256, 2) void gemm_qkvwf(
    const float* __restrict__ Wq_l, const float* __restrict__ Wk_l,
    const float* __restrict__ Wv_l, const float* __restrict__ Wq_r,
    const float* __restrict__ Wk_r, const float* __restrict__ Wv_r,
    const float* __restrict__ left, const float* __restrict__ right,
    const float* __restrict__ W1, const float* __restrict__ Wo,
    float* __restrict__ wf, float qscale)
{
    extern __shared__ __align__(16) unsigned smp[];
    const int z = blockIdx.z;
    if (z == 12) {
        int tt = blockIdx.y * 16 + blockIdx.x;   // 0..127
        gemm_body(W1, Wo, wf, nullptr, nullptr, 0,
                  (tt >> 3) << 7, (tt & 7) << 7,
                  2 * EE, EE, EE, nullptr, 1.f, 0, smp);
        return;
    }
    const int which = z >> 1, b = z & 1;
    const int path = which / 3, kind = which % 3;
    const float* Ws[6] = {Wq_l, Wk_l, Wv_l, Wq_r, Wk_r, Wv_r};
    const float* X = path ? right : left;
    const float alpha = (kind == 0) ? qscale : 1.f;

    unsigned *outh, *outl;
    size_t off;
    int mode;
    if (kind == 2) {   // V: pair over n (s axis)
        mode = 2;
        off = (size_t)path * (BES / 2) + (size_t)b * EE * (SS / 2);
        outh = g_vh + off; outl = g_vlo + off;
    } else {           // Q/K: pair over m (e axis)
        mode = 1;
        off = (size_t)path * (BES / 2) + (size_t)b * (EE / 2) * SS;
        if (kind == 0) { outh = g_qh + off; outl = g_qlo + off; }
        else           { outh = g_kh + off; outl = g_klo + off; }
    }
    gemm_body(Ws[which], X + (size_t)b * EE * SS, nullptr, outh, outl, mode,
              blockIdx.y << 7, blockIdx.x << 7,
              EE, EE, SS, nullptr, alpha, 0, smp);
}

// ---------------------------------------------------------------------------
// Tensor-core flash attention — verified compute; K/V tiles now DOUBLE-
// BUFFERED via cp.async from the packed planes (zero-register, fully
// overlapped with the mma/softmax body).
// SMEM words: Q hi[0..4095] lo[4096..8191]; stage s at 8192+s*8192:
//   Kh +0, Klo +2048, Vh +4096, Vlo +6144.  Total 24576 words = 96KB.
// ---------------------------------------------------------------------------
#define ATTN_SMEM (24576 * 4)

__global__ __launch_bounds__(256, 2) void attn_mma(
    float* __restrict__ Olp, float* __restrict__ Orp)
{
    extern __shared__ __align__(16) unsigned smw[];
    unsigned* Qh = smw;
    unsigned* Qlo = smw + 4096;
    const unsigned sb = (unsigned)__cvta_generic_to_shared(smw);

    const int tid = threadIdx.x;
    const int lane = tid & 31, w = tid >> 5;
    const int path = blockIdx.z >> 1;
    const int bz = blockIdx.z & 1;
    float* O = path ? Orp : Olp;

    const int qt = (gridDim.x - 1) - blockIdx.x;   // heavy tiles first
    const int q0 = qt << 7;
    const size_t poff = (size_t)path * (BES / 2);
    const size_t base2 = poff + ((size_t)bz * (EE / 2) + (size_t)blockIdx.y * 32) * SS;
    const size_t baseV = poff + ((size_t)bz * EE + (size_t)blockIdx.y * DD) * (SS / 2);
    const size_t baseO = ((size_t)bz * EE + (size_t)blockIdx.y * DD) * SS;

    // stage a K/V tile (t0) into buffer stg via cp.async; commits one group
    auto stageKV = [&](int t0, int stg) {
        const unsigned so = 8192 + stg * 8192;
#pragma unroll
        for (int i = 0; i < 4; ++i) {
            int s = tid + (i << 8);
            int ls = s & 31, kc = (s >> 5) & 3, nt = s >> 7;
            int tt = t0 + (nt << 3) + (ls >> 2);
            int e2 = (kc << 3) + (ls & 3);
            const unsigned* ph = g_kh + base2 + (size_t)e2 * SS;
            const unsigned* pl = g_klo + base2 + (size_t)e2 * SS;
            unsigned dh = sb + (so + s * 2) * 4;
            unsigned dl = sb + (so + 2048 + s * 2) * 4;
            cpa4(dh,     ph + tt);
            cpa4(dh + 4, ph + (size_t)4 * SS + tt);
            cpa4(dl,     pl + tt);
            cpa4(dl + 4, pl + (size_t)4 * SS + tt);
        }
#pragma unroll
        for (int i = 0; i < 4; ++i) {
            int s = tid + (i << 8);
            int ls = s & 31, tc = (s >> 5) & 3, ndt = s >> 7;
            int d = (ndt << 3) + (ls >> 2);
            int t2 = (t0 >> 1) + (tc << 3) + (ls & 3);
            const unsigned* ph = g_vh + baseV + (size_t)d * (SS / 2);
            const unsigned* pl = g_vlo + baseV + (size_t)d * (SS / 2);
            unsigned dh = sb + (so + 4096 + s * 2) * 4;
            unsigned dl = sb + (so + 6144 + s * 2) * 4;
            cpa4(dh,     ph + t2);
            cpa4(dh + 4, ph + t2 + 4);
            cpa4(dl,     pl + t2);
            cpa4(dl + 4, pl + t2 + 4);
        }
        asm volatile("cp.async.commit_group;" ::: "memory");
    };

    const int ntile = qt * 2 + 2;
    stageKV(0, 0);   // tile 0 in flight

    // ---- Q fragments (once per block): word loads from packed planes ----
#pragma unroll
    for (int i = 0; i < 4; ++i) {
        int s = tid + (i << 8);
        int ls = s & 31, kc = (s >> 5) & 3, wq = s >> 7;
        int qr_ = q0 + (wq << 4) + (ls >> 2);
        int e2 = (kc << 3) + (ls & 3);
        const unsigned* ph = g_qh + base2 + (size_t)e2 * SS;
        const unsigned* pl = g_qlo + base2 + (size_t)e2 * SS;
        *(uint4*)&Qh[s * 4] = make_uint4(ph[qr_], ph[qr_ + 8],
                                         ph[(size_t)4 * SS + qr_],
                                         ph[(size_t)4 * SS + qr_ + 8]);
        *(uint4*)&Qlo[s * 4] = make_uint4(pl[qr_], pl[qr_ + 8],
                                          pl[(size_t)4 * SS + qr_],
                                          pl[(size_t)4 * SS + qr_ + 8]);
    }

    float o[8][4];
#pragma unroll
    for (int i = 0; i < 8; ++i)
#pragma unroll
        for (int j = 0; j < 4; ++j) o[i][j] = 0.f;
    float m0 = -1e30f, m1 = -1e30f, l0s = 0.f, l1s = 0.f;

    const int qg = q0 + (w << 4) + (lane >> 2);

    for (int kt = 0; kt < ntile; ++kt) {
        const int t0 = kt << 6;
        const int cur = kt & 1;
        if (kt + 1 < ntile) {
            stageKV((kt + 1) << 6, cur ^ 1);
            asm volatile("cp.async.wait_group 1;" ::: "memory");
        } else {
            asm volatile("cp.async.wait_group 0;" ::: "memory");
        }
        __syncthreads();   // tile kt visible to all threads

        const unsigned so = 8192 + cur * 8192;
        const unsigned* Kh = smw + so;
        const unsigned* Klo = smw + so + 2048;
        const unsigned* Vh = smw + so + 4096;
        const unsigned* Vlo = smw + so + 6144;

        float sreg[8][4];
#pragma unroll
        for (int i = 0; i < 8; ++i)
#pragma unroll
            for (int j = 0; j < 4; ++j) sreg[i][j] = 0.f;
#pragma unroll
        for (int kc = 0; kc < 4; ++kc) {
            int ai = ((w * 4 + kc) * 32 + lane);
            uint4 ah = *(const uint4*)&Qh[ai * 4];
            uint4 al = *(const uint4*)&Qlo[ai * 4];
#pragma unroll
            for (int nt = 0; nt < 8; ++nt) {
                int bi = ((nt * 4 + kc) * 32 + lane);
                uint2 bh = *(const uint2*)&Kh[bi * 2];
                uint2 bl = *(const uint2*)&Klo[bi * 2];
                float* c = sreg[nt];
                mma_bf16(c[0], c[1], c[2], c[3], ah.x, ah.y, ah.z, ah.w, bh.x, bh.y);
                mma_bf16(c[0], c[1], c[2], c[3], ah.x, ah.y, ah.z, ah.w, bl.x, bl.y);
                mma_bf16(c[0], c[1], c[2], c[3], al.x, al.y, al.z, al.w, bh.x, bh.y);
            }
        }

        float mx0 = m0, mx1 = m1;
#pragma unroll
        for (int nt = 0; nt < 8; ++nt) {
            int tb = t0 + (nt << 3) + ((lane & 3) << 1);
            if (tb > qg)     sreg[nt][0] = -1e30f;
            if (tb + 1 > qg) sreg[nt][1] = -1e30f;
            if (tb > qg + 8)     sreg[nt][2] = -1e30f;
            if (tb + 1 > qg + 8) sreg[nt][3] = -1e30f;
            mx0 = fmaxf(mx0, fmaxf(sreg[nt][0], sreg[nt][1]));
            mx1 = fmaxf(mx1, fmaxf(sreg[nt][2], sreg[nt][3]));
        }
        mx0 = fmaxf(mx0, __shfl_xor_sync(0xffffffffu, mx0, 1));
        mx0 = fmaxf(mx0, __shfl_xor_sync(0xffffffffu, mx0, 2));
        mx1 = fmaxf(mx1, __shfl_xor_sync(0xffffffffu, mx1, 1));
        mx1 = fmaxf(mx1, __shfl_xor_sync(0xffffffffu, mx1, 2));
        float corr0 = exp2p(m0 - mx0), corr1 = exp2p(m1 - mx1);
        m0 = mx0; m1 = mx1;
        l0s *= corr0; l1s *= corr1;
#pragma unroll
        for (int nt = 0; nt < 8; ++nt) {
            o[nt][0] *= corr0; o[nt][1] *= corr0;
            o[nt][2] *= corr1; o[nt][3] *= corr1;
        }
        float ls0 = 0.f, ls1 = 0.f;
#pragma unroll
        for (int nt = 0; nt < 8; ++nt) {
            float p0 = exp2p(sreg[nt][0] - mx0);
            float p1 = exp2p(sreg[nt][1] - mx0);
            float p2 = exp2p(sreg[nt][2] - mx1);
            float p3 = exp2p(sreg[nt][3] - mx1);
            sreg[nt][0] = p0; sreg[nt][1] = p1;
            sreg[nt][2] = p2; sreg[nt][3] = p3;
            ls0 += p0 + p1; ls1 += p2 + p3;
        }
        ls0 += __shfl_xor_sync(0xffffffffu, ls0, 1);
        ls0 += __shfl_xor_sync(0xffffffffu, ls0, 2);
        ls1 += __shfl_xor_sync(0xffffffffu, ls1, 1);
        ls1 += __shfl_xor_sync(0xffffffffu, ls1, 2);
        l0s += ls0; l1s += ls1;

#pragma unroll
        for (int j = 0; j < 4; ++j) {
            float* pA = sreg[2 * j];
            float* pB = sreg[2 * j + 1];
            unsigned ah0 = bf2pack(pA[0], pA[1]);
            unsigned ah1 = bf2pack(pA[2], pA[3]);
            unsigned ah2 = bf2pack(pB[0], pB[1]);
            unsigned ah3 = bf2pack(pB[2], pB[3]);
            unsigned al0 = bf2pack(pA[0] - bfhi(pA[0]), pA[1] - bfhi(pA[1]));
            unsigned al1 = bf2pack(pA[2] - bfhi(pA[2]), pA[3] - bfhi(pA[3]));
            unsigned al2 = bf2pack(pB[0] - bfhi(pB[0]), pB[1] - bfhi(pB[1]));
            unsigned al3 = bf2pack(pB[2] - bfhi(pB[2]), pB[3] - bfhi(pB[3]));
#pragma unroll
            for (int nt = 0; nt < 8; ++nt) {
                int bi = ((nt * 4 + j) * 32 + lane);
                uint2 bh = *(const uint2*)&Vh[bi * 2];
                uint2 bl = *(const uint2*)&Vlo[bi * 2];
                float* c = o[nt];
                mma_bf16(c[0], c[1], c[2], c[3], ah0, ah1, ah2, ah3, bh.x, bh.y);
                mma_bf16(c[0], c[1], c[2], c[3], ah0, ah1, ah2, ah3, bl.x, bl.y);
                mma_bf16(c[0], c[1], c[2], c[3], al0, al1, al2, al3, bh.x, bh.y);
            }
        }
        __syncthreads();   // all reads of buf[cur] done before it is re-staged
    }

    const float inv0 = 1.f / l0s, inv1 = 1.f / l1s;
    float* Op = O + baseO;
#pragma unroll
    for (int nt = 0; nt < 8; ++nt) {
        int d = (nt << 3) + ((lane & 3) << 1);
        Op[(size_t)d * SS + qg]       = o[nt][0] * inv0;
        Op[(size_t)(d + 1) * SS + qg] = o[nt][1] * inv0;
        Op[(size_t)d * SS + qg + 8]       = o[nt][2] * inv1;
        Op[(size_t)(d + 1) * SS + qg + 8] = o[nt][3] * inv1;
    }
}

// ---------------------------------------------------------------------------
// lambda = exp(sum lam_q_l*lam_k_l) - exp(sum lam_q_r*lam_k_r) + 0.1
// ---------------------------------------------------------------------------
__global__ void lam_kernel(const float* __restrict__ ql, const float* __restrict__ kl,
                           const float* __restrict__ qr, const float* __restrict__ kr)
{
    const int t = threadIdx.x;
    float a = ql[t] * kl[t] + ql[t + 32] * kl[t + 32];
    float b = qr[t] * kr[t] + qr[t + 32] * kr[t + 32];
#pragma unroll
    for (int off = 16; off > 0; off >>= 1) {
        a += __shfl_xor_sync(0xffffffffu, a, off);
        b += __shfl_xor_sync(0xffffffffu, b, off);
    }
    if (t == 0) g_lam = expf(a) - expf(b) + 0.1f;
}

// ---------------------------------------------------------------------------
// combined = attn_l - lam*attn_r; LayerNorm over E (biased var, eps 1e-5).
// ---------------------------------------------------------------------------
__global__ __launch_bounds__(512) void ln_kernel(
    const float* __restrict__ al, const float* __restrict__ ar,
    const float* __restrict__ gg, const float* __restrict__ bbv,
    float* __restrict__ out)
{
    __shared__ float ps[16][32], pq[16][32], smu[32], srs[32];
    const int tid = threadIdx.x;
    const int ty = tid >> 5, sl = tid & 31;
    const int b = blockIdx.x >> 6;
    const int s = ((blockIdx.x & 63) << 5) + sl;
    const float lam = g_lam;
    const size_t col = (size_t)b * EE * SS + s;
    const int e0 = ty << 6;

    float sum = 0.f, sq = 0.f;
    for (int e = e0; e < e0 + 64; ++e) {
        size_t idx = col + (size_t)e * SS;
        float c = al[idx] - lam * ar[idx];
        sum += c; sq += c * c;
    }
    ps[ty][sl] = sum; pq[ty][sl] = sq;
    __syncthreads();
    if (ty == 0) {
        float ts = 0.f, tq = 0.f;
#pragma unroll
        for (int r = 0; r < 16; ++r) { ts += ps[r][sl]; tq += pq[r][sl]; }
        float mu = ts * (1.f / EE);
        float var = tq * (1.f / EE) - mu * mu;
        smu[sl] = mu;
        srs[sl] = rsqrtf(var + 1e-5f);
    }
    __syncthreads();
    const float mu = smu[sl], rs = srs[sl];
    for (int e = e0; e < e0 + 64; ++e) {
        size_t idx = col + (size_t)e * SS;
        float c = al[idx] - lam * ar[idx];
        out[idx] = (c - mu) * rs * gg[e] + bbv[e];
    }
}

// ---------------------------------------------------------------------------
// Launch
// ---------------------------------------------------------------------------
static float* sym_addr(const void* symbol)
{
    void* p = nullptr;
    cudaGetSymbolAddress(&p, symbol);
    return (float*)p;
}

extern "C" void kernel_launch(void* const* d_in, const int* in_sizes, int n_in,
                              void* d_out, int out_size)
{
    const float* left  = (const float*)d_in[0];
    const float* right = (const float*)d_in[1];
    const float* Wq_l  = (const float*)d_in[2];
    const float* Wk_l  = (const float*)d_in[3];
    const float* Wv_l  = (const float*)d_in[4];
    const float* Wq_r  = (const float*)d_in[5];
    const float* Wk_r  = (const float*)d_in[6];
    const float* Wv_r  = (const float*)d_in[7];
    const float* Wo    = (const float*)d_in[8];
    const float* lql   = (const float*)d_in[9];
    const float* lkl   = (const float*)d_in[10];
    const float* lqr   = (const float*)d_in[11];
    const float* lkr   = (const float*)d_in[12];
    const float* ln_g  = (const float*)d_in[13];
    const float* ln_b  = (const float*)d_in[14];
    const float* W1    = (const float*)d_in[15];
    const float* b1    = (const float*)d_in[16];
    const float* W2    = (const float*)d_in[17];
    const float* b2    = (const float*)d_in[18];
    float* out = (float*)d_out;

    float* al = sym_addr(g_al); float* ar = sym_addr(g_ar);
    float* lno = sym_addr(g_lnout);
    float* h1 = sym_addr(g_h1);
    float* wf = sym_addr(g_wf);

    // D^-0.5 * log2(e): scores in log2 domain (softmax-invariant)
    const float qscale = 0.125f * 1.4426950408889634f;

    cudaFuncSetAttribute(gemm_tc, cudaFuncAttributeMaxDynamicSharedMemorySize,
                         GEMM_SMEM);
    cudaFuncSetAttribute(gemm_qkvwf, cudaFuncAttributeMaxDynamicSharedMemorySize,
                         GEMM_SMEM);
    cudaFuncSetAttribute(attn_mma, cudaFuncAttributeMaxDynamicSharedMemorySize,
                         ATTN_SMEM);

    dim3 blk(256);

    // QKV projections + Wf precompute fused into one launch (z = 0..12)
    gemm_qkvwf<<<dim3(SS / 128, EE / 128, 13), blk, GEMM_SMEM>>>(
        Wq_l, Wk_l, Wv_l, Wq_r, Wk_r, Wv_r, left, right, W1, Wo, wf, qscale);

    // attention: both paths in one launch (z = path*2 + b)
    attn_mma<<<dim3(SS / 128, HH, 2 * BB), 256, ATTN_SMEM>>>(al, ar);

    // lambda, combine + LN
    lam_kernel<<<1, 32>>>(lql, lkl, lqr, lkr);
    ln_kernel<<<BB * (SS / 32), 512>>>(al, ar, ln_g, ln_b, lno);

    // fused (W1@Wo) + relu, then W2 straight into d_out ([B,E,S])
    gemm_tc<<<dim3(SS / 128, 2 * EE / 128, BB), blk, GEMM_SMEM>>>(
        wf, lno, h1, 2 * EE, EE, SS, b1, 1.f, 1);
    gemm_tc<<<dim3(SS / 128, EE / 128, BB), blk, GEMM_SMEM>>>(
        W2, h1, out, EE, 2 * EE, SS, b2, 1.f, 0);
}

// round 12
// speedup vs baseline: 1.0900x; 1.0447x over previous
#include <cuda_runtime.h>
#include <cuda_bf16.h>
#include <math.h>

// Problem constants
#define BB 2
#define EE 1024
#define SS 2048
#define HH 16
#define DD 64
#define BES (BB*EE*SS)          // 4,194,304 elements

// ---------------------------------------------------------------------------
// Scratch (device globals; no runtime allocation allowed)
// ---------------------------------------------------------------------------
__device__ float g_ql[BES], g_kl[BES], g_vl[BES];
__device__ float g_qr[BES], g_kr[BES], g_vr[BES];
__device__ float g_al[BES], g_ar[BES];
__device__ float g_lnout[BES];
__device__ float g_h1[2 * BES];
__device__ float g_wf[2 * EE * EE];
__device__ float g_lam;

// ---------------------------------------------------------------------------
// bf16 split helpers
// ---------------------------------------------------------------------------
__device__ __forceinline__ unsigned bf2pack(float x, float y) {
    __nv_bfloat162 h = __floats2bfloat162_rn(x, y);
    return *reinterpret_cast<unsigned*>(&h);
}
__device__ __forceinline__ float bfhi(float x) {
    return __bfloat162float(__float2bfloat16(x));
}
__device__ __forceinline__ void mma_bf16(
    float& c0, float& c1, float& c2, float& c3,
    unsigned a0, unsigned a1, unsigned a2, unsigned a3,
    unsigned b0, unsigned b1)
{
    asm("mma.sync.aligned.m16n8k16.row.col.f32.bf16.bf16.f32 "
        "{%0,%1,%2,%3}, {%4,%5,%6,%7}, {%8,%9}, {%0,%1,%2,%3};"
        : "+f"(c0), "+f"(c1), "+f"(c2), "+f"(c3)
        : "r"(a0), "r"(a1), "r"(a2), "r"(a3), "r"(b0), "r"(b1));
}

// exp2 via FMA-pipe polynomial (degree-5, rel ~2e-6) — dodges MUFU ceiling.
__device__ __forceinline__ float exp2p(float z) {
    z = fmaxf(z, -100.f);
    float n = rintf(z);
    float f = z - n;
    float p = 0.00133335581f;
    p = fmaf(p, f, 0.00961812911f);
    p = fmaf(p, f, 0.05550410866f);
    p = fmaf(p, f, 0.24022650696f);
    p = fmaf(p, f, 0.69314718056f);
    p = fmaf(p, f, 1.0f);
    float sc = __int_as_float(((int)n + 127) << 23);
    return p * sc;
}

// ---------------------------------------------------------------------------
// Tensor-core GEMM body (3-product split-bf16 m16n8k16), double-buffered,
// two-pass compute (round-8 verified; measured best). bm/bn passed in so a
// fused launch can remap tiles.
// Per-buffer word layout: Ah[0..1023] Al[1024..2047] Bh[2048..3071] Bl[3072..4095]
// ---------------------------------------------------------------------------
#define GEMM_SMEM (2 * 4096 * 4)

__device__ __forceinline__ void gemm_body(
    const float* __restrict__ W, const float* __restrict__ Xb,
    float* __restrict__ Cb, int bm, int bn,
    int M, int K, int N, const float* __restrict__ bias, float alpha, int relu,
    unsigned* smp)
{
    const int t = threadIdx.x;
    const int lane = t & 31, wid = t >> 5;
    const int warpM = wid >> 2, warpN = wid & 3;

    float acc[4][4][4];
#pragma unroll
    for (int a = 0; a < 4; ++a)
#pragma unroll
        for (int b = 0; b < 4; ++b)
#pragma unroll
            for (int c = 0; c < 4; ++c) acc[a][b][c] = 0.f;

    const int amt = t >> 5, als = t & 31;
    const int amo = (amt << 4) + (als >> 2);
    const int ako = (als & 3) << 1;
    int bno[2], bko[2];
#pragma unroll
    for (int i = 0; i < 2; ++i) {
        int s = t + (i << 8), nt = s >> 5, ls = s & 31;
        bno[i] = (nt << 3) + (ls >> 2);
        bko[i] = (ls & 3) << 1;
    }

    float2 pa[4];
    float2 pb[2][2];

    auto loadG = [&](int k0) {
        const float* ap = W + (size_t)(bm + amo) * K + (k0 + ako);
        pa[0] = *(const float2*)ap;
        pa[1] = *(const float2*)(ap + (size_t)8 * K);
        pa[2] = *(const float2*)(ap + 8);
        pa[3] = *(const float2*)(ap + (size_t)8 * K + 8);
#pragma unroll
        for (int i = 0; i < 2; ++i) {
            const float* bp = Xb + (size_t)(k0 + bko[i]) * N + bn + bno[i];
            pb[i][0] = make_float2(bp[0], bp[N]);
            pb[i][1] = make_float2(bp[(size_t)8 * N], bp[(size_t)9 * N]);
        }
    };

    auto storeS = [&](int buf) {
        unsigned* Ah = smp + buf * 4096;
        unsigned* Al = smp + buf * 4096 + 1024;
        unsigned* Bh = smp + buf * 4096 + 2048;
        unsigned* Bl = smp + buf * 4096 + 3072;
        {
            unsigned h[4], l[4];
#pragma unroll
            for (int r = 0; r < 4; ++r) {
                float hx = bfhi(pa[r].x), hy = bfhi(pa[r].y);
                h[r] = bf2pack(pa[r].x, pa[r].y);
                l[r] = bf2pack(pa[r].x - hx, pa[r].y - hy);
            }
            *(uint4*)&Ah[t * 4] = make_uint4(h[0], h[1], h[2], h[3]);
            *(uint4*)&Al[t * 4] = make_uint4(l[0], l[1], l[2], l[3]);
        }
#pragma unroll
        for (int i = 0; i < 2; ++i) {
            int s = t + (i << 8);
            float hx = bfhi(pb[i][0].x), hy = bfhi(pb[i][0].y);
            unsigned h0 = bf2pack(pb[i][0].x, pb[i][0].y);
            unsigned l0 = bf2pack(pb[i][0].x - hx, pb[i][0].y - hy);
            hx = bfhi(pb[i][1].x); hy = bfhi(pb[i][1].y);
            unsigned h1 = bf2pack(pb[i][1].x, pb[i][1].y);
            unsigned l1 = bf2pack(pb[i][1].x - hx, pb[i][1].y - hy);
            *(uint2*)&Bh[s * 2] = make_uint2(h0, h1);
            *(uint2*)&Bl[s * 2] = make_uint2(l0, l1);
        }
    };

    // Two-pass compute: pass1 = Ah x (Bh, Bl); pass2 = Al x Bh.
    auto compute = [&](int buf) {
        const unsigned* Ah = smp + buf * 4096;
        const unsigned* Al = smp + buf * 4096 + 1024;
        const unsigned* Bh = smp + buf * 4096 + 2048;
        const unsigned* Bl = smp + buf * 4096 + 3072;
        uint4 af[4];
#pragma unroll
        for (int mt = 0; mt < 4; ++mt)
            af[mt] = *(const uint4*)&Ah[((warpM * 4 + mt) * 32 + lane) * 4];
#pragma unroll
        for (int nt = 0; nt < 4; ++nt) {
            int idx = (warpN * 4 + nt) * 32 + lane;
            uint2 bh = *(const uint2*)&Bh[idx * 2];
            uint2 bl = *(const uint2*)&Bl[idx * 2];
#pragma unroll
            for (int mt = 0; mt < 4; ++mt) {
                float* c = acc[mt][nt];
                mma_bf16(c[0], c[1], c[2], c[3],
                         af[mt].x, af[mt].y, af[mt].z, af[mt].w, bh.x, bh.y);
                mma_bf16(c[0], c[1], c[2], c[3],
                         af[mt].x, af[mt].y, af[mt].z, af[mt].w, bl.x, bl.y);
            }
        }
#pragma unroll
        for (int mt = 0; mt < 4; ++mt)
            af[mt] = *(const uint4*)&Al[((warpM * 4 + mt) * 32 + lane) * 4];
#pragma unroll
        for (int nt = 0; nt < 4; ++nt) {
            int idx = (warpN * 4 + nt) * 32 + lane;
            uint2 bh = *(const uint2*)&Bh[idx * 2];
#pragma unroll
            for (int mt = 0; mt < 4; ++mt) {
                float* c = acc[mt][nt];
                mma_bf16(c[0], c[1], c[2], c[3],
                         af[mt].x, af[mt].y, af[mt].z, af[mt].w, bh.x, bh.y);
            }
        }
    };

    const int kiters = K >> 4;
    loadG(0);
    storeS(0);
    __syncthreads();
    for (int it = 0; it < kiters; ++it) {
        const int cur = it & 1;
        if (it + 1 < kiters) loadG((it + 1) << 4);
        compute(cur);
        if (it + 1 < kiters) storeS(cur ^ 1);
        __syncthreads();
    }

    const int r = lane >> 2, j = lane & 3;
#pragma unroll
    for (int mt = 0; mt < 4; ++mt) {
        const int m0 = bm + warpM * 64 + mt * 16 + r;
        const float bv0 = bias ? bias[m0] : 0.f;
        const float bv1 = bias ? bias[m0 + 8] : 0.f;
#pragma unroll
        for (int nt = 0; nt < 4; ++nt) {
            const int n = bn + warpN * 32 + nt * 8 + j * 2;
            const float* c = acc[mt][nt];
            float r0 = alpha * c[0] + bv0, r1 = alpha * c[1] + bv0;
            float r2 = alpha * c[2] + bv1, r3 = alpha * c[3] + bv1;
            if (relu) {
                r0 = fmaxf(r0, 0.f); r1 = fmaxf(r1, 0.f);
                r2 = fmaxf(r2, 0.f); r3 = fmaxf(r3, 0.f);
            }
            *(float2*)&Cb[(size_t)m0 * N + n] = make_float2(r0, r1);
            *(float2*)&Cb[(size_t)(m0 + 8) * N + n] = make_float2(r2, r3);
        }
    }
}

__global__ __launch_bounds__(256, 2) void gemm_tc(
    const float* __restrict__ W, const float* __restrict__ X,
    float* __restrict__ C, int M, int K, int N,
    const float* __restrict__ bias, float alpha, int relu)
{
    extern __shared__ __align__(16) unsigned smp[];
    gemm_body(W, X + (size_t)blockIdx.z * K * N, C + (size_t)blockIdx.z * M * N,
              blockIdx.y << 7, blockIdx.x << 7, M, K, N, bias, alpha, relu, smp);
}

// QKV projections (z 0..11) + Wf=W1@Wo (z==12, its 128 tiles remapped onto
// the 16x8 xy slots) in ONE launch — removes the serial half-occupancy
// Wf launch from the critical path.
__global__ __launch_bounds__(256, 2) void gemm_qkvwf(
    const float* __restrict__ Wq_l, const float* __restrict__ Wk_l,
    const float* __restrict__ Wv_l, const float* __restrict__ Wq_r,
    const float* __restrict__ Wk_r, const float* __restrict__ Wv_r,
    const float* __restrict__ left, const float* __restrict__ right,
    const float* __restrict__ W1, const float* __restrict__ Wo,
    float* __restrict__ wf,
    float* ql, float* kl, float* vl, float* qr, float* kr, float* vr,
    float qscale)
{
    extern __shared__ __align__(16) unsigned smp[];
    const int z = blockIdx.z;
    if (z == 12) {
        // Wf: M=2048, N=1024 -> 16x8 = 128 tiles; xy grid is 16x8 = 128 slots
        int tt = blockIdx.y * 16 + blockIdx.x;   // 0..127
        gemm_body(W1, Wo, wf, (tt >> 3) << 7, (tt & 7) << 7,
                  2 * EE, EE, EE, nullptr, 1.f, 0, smp);
        return;
    }
    const int which = z >> 1, b = z & 1;
    const float* Ws[6] = {Wq_l, Wk_l, Wv_l, Wq_r, Wk_r, Wv_r};
    float*       Cs[6] = {ql, kl, vl, qr, kr, vr};
    const float* X = (which < 3) ? left : right;
    const float alpha = (which == 0 || which == 3) ? qscale : 1.f;
    gemm_body(Ws[which], X + (size_t)b * EE * SS, Cs[which] + (size_t)b * EE * SS,
              blockIdx.y << 7, blockIdx.x << 7, EE, EE, SS, nullptr, alpha, 0, smp);
}

// ---------------------------------------------------------------------------
// Tensor-core flash attention (causal), split-bf16 3-product, FA2 fragment
// chaining, log2-domain softmax via exp2p. (round-8 verified, unchanged)
// ---------------------------------------------------------------------------
#define ATTN_SMEM (16384 * 4)

__global__ __launch_bounds__(256, 2) void attn_mma(
    const float* __restrict__ Qlp, const float* __restrict__ Klp,
    const float* __restrict__ Vlp, float* __restrict__ Olp,
    const float* __restrict__ Qrp, const float* __restrict__ Krp,
    const float* __restrict__ Vrp, float* __restrict__ Orp)
{
    extern __shared__ __align__(16) unsigned smw[];
    unsigned* Qh = smw;            // 4096
    unsigned* Qlo = smw + 4096;    // 4096
    unsigned* Kh = smw + 8192;     // 2048
    unsigned* Klo = smw + 10240;   // 2048
    unsigned* Vh = smw + 12288;    // 2048
    unsigned* Vlo = smw + 14336;   // 2048

    const int tid = threadIdx.x;
    const int lane = tid & 31, w = tid >> 5;
    const int path = blockIdx.z >> 1;
    const int bz = blockIdx.z & 1;
    const float* Q = path ? Qrp : Qlp;
    const float* Kg = path ? Krp : Klp;
    const float* V = path ? Vrp : Vlp;
    float* O = path ? Orp : Olp;

    const int qt = (gridDim.x - 1) - blockIdx.x;
    const int q0 = qt << 7;
    const size_t base = ((size_t)bz * EE + (size_t)blockIdx.y * DD) * SS;
    const float* Qp = Q + base;
    const float* Kp = Kg + base;
    const float* Vp = V + base;

#pragma unroll
    for (int i = 0; i < 4; ++i) {
        int s = tid + (i << 8);
        int ls = s & 31, kc = (s >> 5) & 3, wq = s >> 7;
        int qr_ = q0 + (wq << 4) + (ls >> 2);
        int d0 = (kc << 4) + ((ls & 3) << 1);
        const float* p00 = Qp + (size_t)d0 * SS + qr_;
        float f0a = p00[0],              f0b = p00[SS];
        float f1a = p00[8],              f1b = p00[SS + 8];
        float f2a = p00[(size_t)8 * SS], f2b = p00[(size_t)9 * SS];
        float f3a = p00[(size_t)8 * SS + 8], f3b = p00[(size_t)9 * SS + 8];
        unsigned h0 = bf2pack(f0a, f0b), h1 = bf2pack(f1a, f1b);
        unsigned h2 = bf2pack(f2a, f2b), h3 = bf2pack(f3a, f3b);
        unsigned l0 = bf2pack(f0a - bfhi(f0a), f0b - bfhi(f0b));
        unsigned l1 = bf2pack(f1a - bfhi(f1a), f1b - bfhi(f1b));
        unsigned l2 = bf2pack(f2a - bfhi(f2a), f2b - bfhi(f2b));
        unsigned l3 = bf2pack(f3a - bfhi(f3a), f3b - bfhi(f3b));
        *(uint4*)&Qh[s * 4]  = make_uint4(h0, h1, h2, h3);
        *(uint4*)&Qlo[s * 4] = make_uint4(l0, l1, l2, l3);
    }

    float o[8][4];
#pragma unroll
    for (int i = 0; i < 8; ++i)
#pragma unroll
        for (int j = 0; j < 4; ++j) o[i][j] = 0.f;
    float m0 = -1e30f, m1 = -1e30f, l0s = 0.f, l1s = 0.f;

    const int qg = q0 + (w << 4) + (lane >> 2);
    const int ntile = qt * 2 + 2;

    for (int kt = 0; kt < ntile; ++kt) {
        const int t0 = kt << 6;
        __syncthreads();
#pragma unroll
        for (int i = 0; i < 4; ++i) {
            int s = tid + (i << 8);
            int ls = s & 31, kc = (s >> 5) & 3, nt = s >> 7;
            int tt = t0 + (nt << 3) + (ls >> 2);
            int d0 = (kc << 4) + ((ls & 3) << 1);
            const float* p00 = Kp + (size_t)d0 * SS + tt;
            float f0a = p00[0], f0b = p00[SS];
            float f1a = p00[(size_t)8 * SS], f1b = p00[(size_t)9 * SS];
            *(uint2*)&Kh[s * 2] = make_uint2(bf2pack(f0a, f0b), bf2pack(f1a, f1b));
            *(uint2*)&Klo[s * 2] = make_uint2(
                bf2pack(f0a - bfhi(f0a), f0b - bfhi(f0b)),
                bf2pack(f1a - bfhi(f1a), f1b - bfhi(f1b)));
        }
#pragma unroll
        for (int i = 0; i < 4; ++i) {
            int s = tid + (i << 8);
            int ls = s & 31, tc = (s >> 5) & 3, ndt = s >> 7;
            int d = (ndt << 3) + (ls >> 2);
            int tt = t0 + (tc << 4) + ((ls & 3) << 1);
            const float* p00 = Vp + (size_t)d * SS + tt;
            float2 v0 = *(const float2*)p00;
            float2 v1 = *(const float2*)(p00 + 8);
            *(uint2*)&Vh[s * 2] = make_uint2(bf2pack(v0.x, v0.y), bf2pack(v1.x, v1.y));
            *(uint2*)&Vlo[s * 2] = make_uint2(
                bf2pack(v0.x - bfhi(v0.x), v0.y - bfhi(v0.y)),
                bf2pack(v1.x - bfhi(v1.x), v1.y - bfhi(v1.y)));
        }
        __syncthreads();

        float sreg[8][4];
#pragma unroll
        for (int i = 0; i < 8; ++i)
#pragma unroll
            for (int j = 0; j < 4; ++j) sreg[i][j] = 0.f;
#pragma unroll
        for (int kc = 0; kc < 4; ++kc) {
            int ai = ((w * 4 + kc) * 32 + lane);
            uint4 ah = *(const uint4*)&Qh[ai * 4];
            uint4 al = *(const uint4*)&Qlo[ai * 4];
#pragma unroll
            for (int nt = 0; nt < 8; ++nt) {
                int bi = ((nt * 4 + kc) * 32 + lane);
                uint2 bh = *(const uint2*)&Kh[bi * 2];
                uint2 bl = *(const uint2*)&Klo[bi * 2];
                float* c = sreg[nt];
                mma_bf16(c[0], c[1], c[2], c[3], ah.x, ah.y, ah.z, ah.w, bh.x, bh.y);
                mma_bf16(c[0], c[1], c[2], c[3], ah.x, ah.y, ah.z, ah.w, bl.x, bl.y);
                mma_bf16(c[0], c[1], c[2], c[3], al.x, al.y, al.z, al.w, bh.x, bh.y);
            }
        }

        float mx0 = m0, mx1 = m1;
#pragma unroll
        for (int nt = 0; nt < 8; ++nt) {
            int tb = t0 + (nt << 3) + ((lane & 3) << 1);
            if (tb > qg)     sreg[nt][0] = -1e30f;
            if (tb + 1 > qg) sreg[nt][1] = -1e30f;
            if (tb > qg + 8)     sreg[nt][2] = -1e30f;
            if (tb + 1 > qg + 8) sreg[nt][3] = -1e30f;
            mx0 = fmaxf(mx0, fmaxf(sreg[nt][0], sreg[nt][1]));
            mx1 = fmaxf(mx1, fmaxf(sreg[nt][2], sreg[nt][3]));
        }
        mx0 = fmaxf(mx0, __shfl_xor_sync(0xffffffffu, mx0, 1));
        mx0 = fmaxf(mx0, __shfl_xor_sync(0xffffffffu, mx0, 2));
        mx1 = fmaxf(mx1, __shfl_xor_sync(0xffffffffu, mx1, 1));
        mx1 = fmaxf(mx1, __shfl_xor_sync(0xffffffffu, mx1, 2));
        float corr0 = exp2p(m0 - mx0), corr1 = exp2p(m1 - mx1);
        m0 = mx0; m1 = mx1;
        l0s *= corr0; l1s *= corr1;
#pragma unroll
        for (int nt = 0; nt < 8; ++nt) {
            o[nt][0] *= corr0; o[nt][1] *= corr0;
            o[nt][2] *= corr1; o[nt][3] *= corr1;
        }
        float ls0 = 0.f, ls1 = 0.f;
#pragma unroll
        for (int nt = 0; nt < 8; ++nt) {
            float p0 = exp2p(sreg[nt][0] - mx0);
            float p1 = exp2p(sreg[nt][1] - mx0);
            float p2 = exp2p(sreg[nt][2] - mx1);
            float p3 = exp2p(sreg[nt][3] - mx1);
            sreg[nt][0] = p0; sreg[nt][1] = p1;
            sreg[nt][2] = p2; sreg[nt][3] = p3;
            ls0 += p0 + p1; ls1 += p2 + p3;
        }
        ls0 += __shfl_xor_sync(0xffffffffu, ls0, 1);
        ls0 += __shfl_xor_sync(0xffffffffu, ls0, 2);
        ls1 += __shfl_xor_sync(0xffffffffu, ls1, 1);
        ls1 += __shfl_xor_sync(0xffffffffu, ls1, 2);
        l0s += ls0; l1s += ls1;

#pragma unroll
        for (int j = 0; j < 4; ++j) {
            float* pA = sreg[2 * j];
            float* pB = sreg[2 * j + 1];
            unsigned ah0 = bf2pack(pA[0], pA[1]);
            unsigned ah1 = bf2pack(pA[2], pA[3]);
            unsigned ah2 = bf2pack(pB[0], pB[1]);
            unsigned ah3 = bf2pack(pB[2], pB[3]);
            unsigned al0 = bf2pack(pA[0] - bfhi(pA[0]), pA[1] - bfhi(pA[1]));
            unsigned al1 = bf2pack(pA[2] - bfhi(pA[2]), pA[3] - bfhi(pA[3]));
            unsigned al2 = bf2pack(pB[0] - bfhi(pB[0]), pB[1] - bfhi(pB[1]));
            unsigned al3 = bf2pack(pB[2] - bfhi(pB[2]), pB[3] - bfhi(pB[3]));
#pragma unroll
            for (int nt = 0; nt < 8; ++nt) {
                int bi = ((nt * 4 + j) * 32 + lane);
                uint2 bh = *(const uint2*)&Vh[bi * 2];
                uint2 bl = *(const uint2*)&Vlo[bi * 2];
                float* c = o[nt];
                mma_bf16(c[0], c[1], c[2], c[3], ah0, ah1, ah2, ah3, bh.x, bh.y);
                mma_bf16(c[0], c[1], c[2], c[3], ah0, ah1, ah2, ah3, bl.x, bl.y);
                mma_bf16(c[0], c[1], c[2], c[3], al0, al1, al2, al3, bh.x, bh.y);
            }
        }
    }

    const float inv0 = 1.f / l0s, inv1 = 1.f / l1s;
    float* Op = O + base;
#pragma unroll
    for (int nt = 0; nt < 8; ++nt) {
        int d = (nt << 3) + ((lane & 3) << 1);
        Op[(size_t)d * SS + qg]       = o[nt][0] * inv0;
        Op[(size_t)(d + 1) * SS + qg] = o[nt][1] * inv0;
        Op[(size_t)d * SS + qg + 8]       = o[nt][2] * inv1;
        Op[(size_t)(d + 1) * SS + qg + 8] = o[nt][3] * inv1;
    }
}

// ---------------------------------------------------------------------------
// lambda = exp(sum lam_q_l*lam_k_l) - exp(sum lam_q_r*lam_k_r) + 0.1
// ---------------------------------------------------------------------------
__global__ void lam_kernel(const float* __restrict__ ql, const float* __restrict__ kl,
                           const float* __restrict__ qr, const float* __restrict__ kr)
{
    const int t = threadIdx.x;
    float a = ql[t] * kl[t] + ql[t + 32] * kl[t + 32];
    float b = qr[t] * kr[t] + qr[t + 32] * kr[t + 32];
#pragma unroll
    for (int off = 16; off > 0; off >>= 1) {
        a += __shfl_xor_sync(0xffffffffu, a, off);
        b += __shfl_xor_sync(0xffffffffu, b, off);
    }
    if (t == 0) g_lam = expf(a) - expf(b) + 0.1f;
}

// ---------------------------------------------------------------------------
// combined = attn_l - lam*attn_r; LayerNorm over E (biased var, eps 1e-5).
// ---------------------------------------------------------------------------
__global__ __launch_bounds__(512) void ln_kernel(
    const float* __restrict__ al, const float* __restrict__ ar,
    const float* __restrict__ gg, const float* __restrict__ bbv,
    float* __restrict__ out)
{
    __shared__ float ps[16][32], pq[16][32], smu[32], srs[32];
    const int tid = threadIdx.x;
    const int ty = tid >> 5, sl = tid & 31;
    const int b = blockIdx.x >> 6;
    const int s = ((blockIdx.x & 63) << 5) + sl;
    const float lam = g_lam;
    const size_t col = (size_t)b * EE * SS + s;
    const int e0 = ty << 6;

    float sum = 0.f, sq = 0.f;
    for (int e = e0; e < e0 + 64; ++e) {
        size_t idx = col + (size_t)e * SS;
        float c = al[idx] - lam * ar[idx];
        sum += c; sq += c * c;
    }
    ps[ty][sl] = sum; pq[ty][sl] = sq;
    __syncthreads();
    if (ty == 0) {
        float ts = 0.f, tq = 0.f;
#pragma unroll
        for (int r = 0; r < 16; ++r) { ts += ps[r][sl]; tq += pq[r][sl]; }
        float mu = ts * (1.f / EE);
        float var = tq * (1.f / EE) - mu * mu;
        smu[sl] = mu;
        srs[sl] = rsqrtf(var + 1e-5f);
    }
    __syncthreads();
    const float mu = smu[sl], rs = srs[sl];
    for (int e = e0; e < e0 + 64; ++e) {
        size_t idx = col + (size_t)e * SS;
        float c = al[idx] - lam * ar[idx];
        out[idx] = (c - mu) * rs * gg[e] + bbv[e];
    }
}

// ---------------------------------------------------------------------------
// Launch
// ---------------------------------------------------------------------------
static float* sym_addr(const void* symbol)
{
    void* p = nullptr;
    cudaGetSymbolAddress(&p, symbol);
    return (float*)p;
}

extern "C" void kernel_launch(void* const* d_in, const int* in_sizes, int n_in,
                              void* d_out, int out_size)
{
    const float* left  = (const float*)d_in[0];
    const float* right = (const float*)d_in[1];
    const float* Wq_l  = (const float*)d_in[2];
    const float* Wk_l  = (const float*)d_in[3];
    const float* Wv_l  = (const float*)d_in[4];
    const float* Wq_r  = (const float*)d_in[5];
    const float* Wk_r  = (const float*)d_in[6];
    const float* Wv_r  = (const float*)d_in[7];
    const float* Wo    = (const float*)d_in[8];
    const float* lql   = (const float*)d_in[9];
    const float* lkl   = (const float*)d_in[10];
    const float* lqr   = (const float*)d_in[11];
    const float* lkr   = (const float*)d_in[12];
    const float* ln_g  = (const float*)d_in[13];
    const float* ln_b  = (const float*)d_in[14];
    const float* W1    = (const float*)d_in[15];
    const float* b1    = (const float*)d_in[16];
    const float* W2    = (const float*)d_in[17];
    const float* b2    = (const float*)d_in[18];
    float* out = (float*)d_out;

    float* ql = sym_addr(g_ql); float* kl = sym_addr(g_kl); float* vl = sym_addr(g_vl);
    float* qr = sym_addr(g_qr); float* kr = sym_addr(g_kr); float* vr = sym_addr(g_vr);
    float* al = sym_addr(g_al); float* ar = sym_addr(g_ar);
    float* lno = sym_addr(g_lnout);
    float* h1 = sym_addr(g_h1);
    float* wf = sym_addr(g_wf);

    // D^-0.5 * log2(e): scores in log2 domain (softmax-invariant)
    const float qscale = 0.125f * 1.4426950408889634f;

    cudaFuncSetAttribute(gemm_tc, cudaFuncAttributeMaxDynamicSharedMemorySize,
                         GEMM_SMEM);
    cudaFuncSetAttribute(gemm_qkvwf, cudaFuncAttributeMaxDynamicSharedMemorySize,
                         GEMM_SMEM);
    cudaFuncSetAttribute(attn_mma, cudaFuncAttributeMaxDynamicSharedMemorySize,
                         ATTN_SMEM);

    dim3 blk(256);

    // QKV projections + Wf=W1@Wo fused into one launch (z = 0..12)
    gemm_qkvwf<<<dim3(SS / 128, EE / 128, 13), blk, GEMM_SMEM>>>(
        Wq_l, Wk_l, Wv_l, Wq_r, Wk_r, Wv_r, left, right, W1, Wo, wf,
        ql, kl, vl, qr, kr, vr, qscale);

    // attention: both paths in one launch (z = path*2 + b)
    attn_mma<<<dim3(SS / 128, HH, 2 * BB), 256, ATTN_SMEM>>>(
        ql, kl, vl, al, qr, kr, vr, ar);

    // lambda, combine + LN
    lam_kernel<<<1, 32>>>(lql, lkl, lqr, lkr);
    ln_kernel<<<BB * (SS / 32), 512>>>(al, ar, ln_g, ln_b, lno);

    // fused (W1@Wo) + relu, then W2 straight into d_out ([B,E,S])
    gemm_tc<<<dim3(SS / 128, 2 * EE / 128, BB), blk, GEMM_SMEM>>>(
        wf, lno, h1, 2 * EE, EE, SS, b1, 1.f, 1);
    gemm_tc<<<dim3(SS / 128, EE / 128, BB), blk, GEMM_SMEM>>>(
        W2, h1, out, EE, 2 * EE, SS, b2, 1.f, 0);
}